// round 1
// baseline (speedup 1.0000x reference)
#include <cuda_runtime.h>
#include <cstdint>

#define NN_ 2048
#define FIN 64
#define G_ 128
#define FOBS 32
#define NG (NN_*G_)
#define NSQ (NN_*NN_)
#define EPSF 1e-10f
#define NSPLIT 8
#define JSPAN (NN_/NSPLIT)   // 256
#define TI 64
#define TJ 32
#define NTJ (JSPAN/TJ)       // 8
#define TIA 8

// ---------------- scratch (static device, no allocs) ----------------
__device__ float g_Afb[NSQ];            // fallback A if out_size too small (16MB)
__device__ float g_H[NG];
__device__ float g_Wh[NG];
__device__ float g_w1[NN_], g_w2[NN_], g_m[NN_];
__device__ float g_cq[G_], g_cv[G_];
__device__ float g_part[NSPLIT][NG];    // deterministic partial accumulators (8MB)
__device__ float g_Zpart[NSPLIT][NN_];

// ---------------- FMA-pipe math (no MUFU) ----------------
__device__ __forceinline__ float fexp(float x) {
    float x2 = x * 1.4426950408889634f;          // -> base 2
    x2 = fminf(fmaxf(x2, -126.0f), 126.0f);
    float r = x2 + 12582912.0f;                  // round-to-nearest int trick
    int   n = __float_as_int(r) - 0x4B400000;
    float f = x2 - (r - 12582912.0f);            // f in [-0.5, 0.5]
    float p = 1.5403512e-4f;
    p = fmaf(p, f, 1.33335574e-3f);
    p = fmaf(p, f, 9.61812911e-3f);
    p = fmaf(p, f, 5.55041087e-2f);
    p = fmaf(p, f, 2.40226507e-1f);
    p = fmaf(p, f, 6.93147181e-1f);
    p = fmaf(p, f, 1.0f);
    return p * __int_as_float((n + 127) << 23);
}

__device__ __forceinline__ float flog(float x) {   // natural log, x in (1e-10, ~1+]
    int ix = __float_as_int(x);
    int e  = (ix >> 23) - 127;
    float m = __int_as_float((ix & 0x007FFFFF) | 0x3F800000);   // [1,2)
    if (m > 1.41421356f) { m *= 0.5f; e += 1; }                 // [0.707,1.414)
    float f = m - 1.0f;
    float p = -0.1f;
    p = fmaf(p, f,  0.111111111f);
    p = fmaf(p, f, -0.125f);
    p = fmaf(p, f,  0.142857143f);
    p = fmaf(p, f, -0.166666667f);
    p = fmaf(p, f,  0.2f);
    p = fmaf(p, f, -0.25f);
    p = fmaf(p, f,  0.333333333f);
    p = fmaf(p, f, -0.5f);
    p = fmaf(p, f,  1.0f);
    p = p * f;
    return fmaf((float)e, 0.69314718056f, p);
}

__device__ __forceinline__ float frcp(float d) {   // d > 0
    float y = __int_as_float(0x7EF311C3 - __float_as_int(d));
    y = y * (2.0f - d * y);
    y = y * (2.0f - d * y);
    y = y * (2.0f - d * y);
    return y;
}

// ---------------- Kernel 1: A = sigmoid((logits+gumbel)/tau), diag=1 ----------------
// A = 1/(1 + exp(-10*l) * t^10),  t = -log(u+eps)+eps   (tau=0.1 exact rewrite)
__global__ __launch_bounds__(256) void k_A(const float* __restrict__ X,
                                           const float* __restrict__ gum,
                                           const float* __restrict__ alink,
                                           float* __restrict__ Ap) {
    __shared__ float sh[TIA][FOBS];
    __shared__ float sa[FOBS];
    int tid = threadIdx.x;
    int i0  = blockIdx.x * TIA;
    if (tid < FOBS) sa[tid] = alink[tid];
    sh[tid >> 5][tid & 31] = X[(i0 + (tid >> 5)) * FIN + (tid & 31)];
    __syncthreads();

    for (int j = tid; j < NN_; j += 256) {
        float xj[FOBS];
        const float4* xp = (const float4*)(X + (size_t)j * FIN);
        #pragma unroll
        for (int q = 0; q < FOBS / 4; q++) ((float4*)xj)[q] = xp[q];

        #pragma unroll
        for (int ii = 0; ii < TIA; ii++) {
            float l = 0.f;
            #pragma unroll
            for (int k = 0; k < FOBS; k++)
                l = fmaf(fabsf(sh[ii][k] - xj[k]), sa[k], l);
            int i = i0 + ii;
            float u = gum[(size_t)i * NN_ + j];
            float t = EPSF - flog(u + EPSF);
            float t2 = t * t, t4 = t2 * t2, t8 = t4 * t4;
            float w = fexp(-10.f * l) * (t8 * t2);
            w = fminf(w, 1e30f);
            float A = frcp(1.0f + w);
            if (j == i) A = 1.0f;
            Ap[(size_t)i * NN_ + j] = A;
        }
    }
}

// ---------------- per-hop small kernels ----------------
// c_q = Wq @ a[:G], c_v = Wv @ a[G:]  (F x 1 each)
__global__ void k_cvec(const float* __restrict__ Wq, const float* __restrict__ Wv,
                       const float* __restrict__ a, int F) {
    int t = threadIdx.x;
    if (t < F) {
        float s1 = 0.f, s2 = 0.f;
        for (int g = 0; g < G_; g++) {
            s1 = fmaf(Wq[t * G_ + g], a[g], s1);
            s2 = fmaf(Wv[t * G_ + g], a[G_ + g], s2);
        }
        g_cq[t] = s1; g_cv[t] = s2;
    }
}

// wh1 = H @ c_q, wh2 = H @ c_v  (warp per row)
__global__ __launch_bounds__(256) void k_wvec(const float* __restrict__ Xp, int hop, int F) {
    const float* H = hop ? g_H : Xp;
    int row  = blockIdx.x * 8 + (threadIdx.x >> 5);
    int lane = threadIdx.x & 31;
    float s1 = 0.f, s2 = 0.f;
    for (int f = lane; f < F; f += 32) {
        float h = H[(size_t)row * F + f];
        s1 = fmaf(h, g_cq[f], s1);
        s2 = fmaf(h, g_cv[f], s2);
    }
    #pragma unroll
    for (int o = 16; o; o >>= 1) {
        s1 += __shfl_xor_sync(0xFFFFFFFFu, s1, o);
        s2 += __shfl_xor_sync(0xFFFFFFFFu, s2, o);
    }
    if (lane == 0) { g_w1[row] = s1; g_w2[row] = s2; }
}

// Wh = H @ Ws  (N x G), thread per output
__global__ __launch_bounds__(256) void k_gemmWh(const float* __restrict__ Xp,
                                                const float* __restrict__ Ws,
                                                int hop, int F) {
    const float* H = hop ? g_H : Xp;
    int idx = blockIdx.x * 256 + threadIdx.x;
    int i = idx >> 7, g = idx & 127;
    float s = 0.f;
    for (int f = 0; f < F; f++)
        s = fmaf(H[(size_t)i * F + f], Ws[f * G_ + g], s);
    g_Wh[idx] = s;
}

// row max of masked e (block per row)
__global__ __launch_bounds__(256) void k_max(const float* __restrict__ Ap) {
    __shared__ float red[256];
    int i = blockIdx.x, tid = threadIdx.x;
    float w1 = g_w1[i];
    float m = -3.4e38f;
    for (int j = tid; j < NN_; j += 256) {
        float a = Ap[(size_t)i * NN_ + j];
        if (a > 0.01f) {
            float e = w1 * g_w2[j];
            e = e > 0.f ? e : 0.2f * e;
            m = fmaxf(m, e);
        }
    }
    red[tid] = m;
    __syncthreads();
    for (int s = 128; s; s >>= 1) {
        if (tid < s) red[tid] = fmaxf(red[tid], red[tid + s]);
        __syncthreads();
    }
    if (tid == 0) g_m[i] = red[0];
}

// fused masked-softmax-numerator x Wh GEMM, deterministic j-split partials
__global__ __launch_bounds__(256) void k_attn(const float* __restrict__ Ap) {
    __shared__ float sWh[TJ][132];
    __shared__ float sP[TI][TJ + 1];
    __shared__ float sm_[TI], sw1[TI];
    __shared__ float szr[TI][4];

    int tid = threadIdx.x;
    int it = blockIdx.x, jt = blockIdx.y;
    int i0 = it * TI;
    if (tid < TI) { sm_[tid] = g_m[i0 + tid]; sw1[tid] = g_w1[i0 + tid]; }
    __syncthreads();

    int prow = tid >> 2, pq = tid & 3;       // P-compute mapping
    int ty = tid >> 4, tx = tid & 15;        // GEMM mapping: 4 rows x 8 cols
    float w1r = sw1[prow], mr = sm_[prow];

    float acc[4][8];
    #pragma unroll
    for (int r = 0; r < 4; r++)
        #pragma unroll
        for (int c = 0; c < 8; c++) acc[r][c] = 0.f;
    float zp = 0.f;

    for (int tt = 0; tt < NTJ; tt++) {
        int j0 = jt * JSPAN + tt * TJ;
        __syncthreads();   // previous GEMM done before overwrite
        // load Wh tile [TJ x 128]
        #pragma unroll
        for (int l = 0; l < (TJ * 128) / 256; l++) {
            int idx = tid + l * 256;
            sWh[idx >> 7][idx & 127] = g_Wh[(size_t)(j0 + (idx >> 7)) * G_ + (idx & 127)];
        }
        // compute P tile
        #pragma unroll
        for (int c = 0; c < 8; c++) {
            int jj = pq * 8 + c;
            int j = j0 + jj;
            float a = Ap[(size_t)(i0 + prow) * NN_ + j];
            float p = 0.f;
            if (a > 0.01f) {
                float e = w1r * g_w2[j];
                e = e > 0.f ? e : 0.2f * e;
                p = fexp(e - mr);
            }
            zp += p;
            sP[prow][jj] = p;
        }
        __syncthreads();
        // GEMM accumulate
        #pragma unroll
        for (int jj = 0; jj < TJ; jj++) {
            float4 b0 = *(const float4*)&sWh[jj][tx * 8];
            float4 b1 = *(const float4*)&sWh[jj][tx * 8 + 4];
            #pragma unroll
            for (int r = 0; r < 4; r++) {
                float p = sP[ty * 4 + r][jj];
                acc[r][0] = fmaf(p, b0.x, acc[r][0]);
                acc[r][1] = fmaf(p, b0.y, acc[r][1]);
                acc[r][2] = fmaf(p, b0.z, acc[r][2]);
                acc[r][3] = fmaf(p, b0.w, acc[r][3]);
                acc[r][4] = fmaf(p, b1.x, acc[r][4]);
                acc[r][5] = fmaf(p, b1.y, acc[r][5]);
                acc[r][6] = fmaf(p, b1.z, acc[r][6]);
                acc[r][7] = fmaf(p, b1.w, acc[r][7]);
            }
        }
    }
    // write partials (race-free: each (it,jt) owns disjoint slice of g_part[jt])
    #pragma unroll
    for (int r = 0; r < 4; r++) {
        float* dst = &g_part[jt][(size_t)(i0 + ty * 4 + r) * G_ + tx * 8];
        *(float4*)dst       = make_float4(acc[r][0], acc[r][1], acc[r][2], acc[r][3]);
        *(float4*)(dst + 4) = make_float4(acc[r][4], acc[r][5], acc[r][6], acc[r][7]);
    }
    szr[prow][pq] = zp;
    __syncthreads();
    if (tid < TI)
        g_Zpart[jt][i0 + tid] = szr[tid][0] + szr[tid][1] + szr[tid][2] + szr[tid][3];
}

// H = relu(acc / Z)
__global__ __launch_bounds__(256) void k_epi(float* __restrict__ dst, int toGlobal) {
    int idx = blockIdx.x * 256 + threadIdx.x;
    int i = idx >> 7;
    float s = 0.f, z = 0.f;
    #pragma unroll
    for (int t = 0; t < NSPLIT; t++) { s += g_part[t][idx]; z += g_Zpart[t][i]; }
    float h = s * frcp(z);
    h = h > 0.f ? h : 0.f;
    if (toGlobal) g_H[idx] = h; else dst[idx] = h;
}

// ---------------- launcher ----------------
extern "C" void kernel_launch(void* const* d_in, const int* in_sizes, int n_in,
                              void* d_out, int out_size) {
    const float* X    = (const float*)d_in[0];
    const float* gum  = (const float*)d_in[1];
    const float* alnk = (const float*)d_in[2];
    const float* Ws[2] = { (const float*)d_in[3], (const float*)d_in[4] };
    const float* Wq[2] = { (const float*)d_in[5], (const float*)d_in[6] };
    const float* Wv[2] = { (const float*)d_in[7], (const float*)d_in[8] };
    const float* aa[2] = { (const float*)d_in[9], (const float*)d_in[10] };
    float* out = (float*)d_out;

    // A location: directly in d_out if it fits, else device fallback
    float* Ap;
    if (out_size >= NG + NSQ) Ap = out + NG;
    else cudaGetSymbolAddress((void**)&Ap, g_Afb);

    // ---- A matrix ----
    k_A<<<NN_ / TIA, 256>>>(X, gum, alnk, Ap);

    // ---- 2 hops ----
    for (int k = 0; k < 2; k++) {
        int F = (k == 0) ? FIN : G_;
        k_cvec<<<1, 128>>>(Wq[k], Wv[k], aa[k], F);
        k_wvec<<<NN_ / 8, 256>>>(X, k, F);
        k_gemmWh<<<NG / 256, 256>>>(X, Ws[k], k, F);
        k_max<<<NN_, 256>>>(Ap);
        dim3 ag(NN_ / TI, NSPLIT);
        k_attn<<<ag, 256>>>(Ap);
        k_epi<<<NG / 256, 256>>>(out, k == 0 ? 1 : 0);   // hop0 -> g_H, hop1 -> out
    }

    // ---- X passthrough ----
    if (out_size >= NG + NSQ + NN_ * FIN)
        cudaMemcpyAsync(out + NG + NSQ, X, (size_t)NN_ * FIN * sizeof(float),
                        cudaMemcpyDeviceToDevice, 0);
}

// round 5
// speedup vs baseline: 1.1300x; 1.1300x over previous
#include <cuda_runtime.h>
#include <cuda_bf16.h>
#include <cstdint>

#define NN_ 2048
#define FIN 64
#define G_ 128
#define FOBS 32
#define NG (NN_*G_)
#define NSQ (NN_*NN_)
#define EPSF 1e-10f
#define TIA 8

#define MT 128
#define JSPLIT 8
#define KSPAN (NN_/JSPLIT)   // 256 j per block
#define KC 32                // j chunk
#define NCH (KSPAN/KC)       // 8

// SMEM padded strides (bf16 elems). Row strides MUST be 16B multiples:
// SAP=40 -> 80B (16-aligned, 20-bank offset: conflict-free ldmatrix)
// SBP=136 -> 272B (16-aligned)
#define SAP 40
#define SBP 136

// ---------------- scratch (static device, no allocs) ----------------
__device__ float g_Afb[NSQ];
__device__ float g_H[NG];
__device__ __nv_bfloat16 g_Whb[NG];           // Wh bf16, [j][g] row-major
__device__ float g_w1[NN_], g_w2[NN_], g_m[NN_];
__device__ float g_cq[G_], g_cv[G_];
__device__ float g_part[JSPLIT][NG];
__device__ float g_Zpart[JSPLIT][NN_];

// ---------------- FMA-pipe math (no MUFU) ----------------
__device__ __forceinline__ float fexp(float x) {
    float x2 = x * 1.4426950408889634f;
    x2 = fminf(fmaxf(x2, -126.0f), 126.0f);
    float r = x2 + 12582912.0f;
    int   n = __float_as_int(r) - 0x4B400000;
    float f = x2 - (r - 12582912.0f);
    float p = 1.5403512e-4f;
    p = fmaf(p, f, 1.33335574e-3f);
    p = fmaf(p, f, 9.61812911e-3f);
    p = fmaf(p, f, 5.55041087e-2f);
    p = fmaf(p, f, 2.40226507e-1f);
    p = fmaf(p, f, 6.93147181e-1f);
    p = fmaf(p, f, 1.0f);
    return p * __int_as_float((n + 127) << 23);
}

__device__ __forceinline__ float flog(float x) {
    int ix = __float_as_int(x);
    int e  = (ix >> 23) - 127;
    float m = __int_as_float((ix & 0x007FFFFF) | 0x3F800000);
    if (m > 1.41421356f) { m *= 0.5f; e += 1; }
    float f = m - 1.0f;
    float p = -0.1f;
    p = fmaf(p, f,  0.111111111f);
    p = fmaf(p, f, -0.125f);
    p = fmaf(p, f,  0.142857143f);
    p = fmaf(p, f, -0.166666667f);
    p = fmaf(p, f,  0.2f);
    p = fmaf(p, f, -0.25f);
    p = fmaf(p, f,  0.333333333f);
    p = fmaf(p, f, -0.5f);
    p = fmaf(p, f,  1.0f);
    p = p * f;
    return fmaf((float)e, 0.69314718056f, p);
}

__device__ __forceinline__ float frcp(float d) {
    float y = __int_as_float(0x7EF311C3 - __float_as_int(d));
    y = y * (2.0f - d * y);
    y = y * (2.0f - d * y);
    y = y * (2.0f - d * y);
    return y;
}

// ---------------- base-ISA tensor-core helpers ----------------
__device__ __forceinline__ uint32_t smem_u32(const void* p) {
    uint32_t a;
    asm("{ .reg .u64 t; cvta.to.shared.u64 t, %1; cvt.u32.u64 %0, t; }" : "=r"(a) : "l"(p));
    return a;
}
__device__ __forceinline__ void ldmA(uint32_t* a, uint32_t addr) {
    asm volatile("ldmatrix.sync.aligned.m8n8.x4.shared.b16 {%0,%1,%2,%3}, [%4];"
                 : "=r"(a[0]), "=r"(a[1]), "=r"(a[2]), "=r"(a[3]) : "r"(addr));
}
__device__ __forceinline__ void ldmB(uint32_t* b, uint32_t addr) {
    asm volatile("ldmatrix.sync.aligned.m8n8.x2.trans.shared.b16 {%0,%1}, [%2];"
                 : "=r"(b[0]), "=r"(b[1]) : "r"(addr));
}
__device__ __forceinline__ void mma16816(float* d, const uint32_t* a, const uint32_t* b) {
    asm volatile("mma.sync.aligned.m16n8k16.row.col.f32.bf16.bf16.f32 "
                 "{%0,%1,%2,%3}, {%4,%5,%6,%7}, {%8,%9}, {%0,%1,%2,%3};"
                 : "+f"(d[0]), "+f"(d[1]), "+f"(d[2]), "+f"(d[3])
                 : "r"(a[0]), "r"(a[1]), "r"(a[2]), "r"(a[3]), "r"(b[0]), "r"(b[1]));
}
__device__ __forceinline__ void sts128(uint32_t addr, uint32_t r0, uint32_t r1, uint32_t r2, uint32_t r3) {
    asm volatile("st.shared.v4.b32 [%0], {%1,%2,%3,%4};"
                 :: "r"(addr), "r"(r0), "r"(r1), "r"(r2), "r"(r3) : "memory");
}

// ---------------- Kernel 1: A matrix ----------------
__global__ __launch_bounds__(256) void k_A(const float* __restrict__ X,
                                           const float* __restrict__ gum,
                                           const float* __restrict__ alink,
                                           float* __restrict__ Ap) {
    __shared__ float sh[TIA][FOBS];
    __shared__ float sa[FOBS];
    int tid = threadIdx.x;
    int i0  = blockIdx.x * TIA;
    if (tid < FOBS) sa[tid] = alink[tid];
    sh[tid >> 5][tid & 31] = X[(i0 + (tid >> 5)) * FIN + (tid & 31)];
    __syncthreads();

    for (int j = tid; j < NN_; j += 256) {
        float xj[FOBS];
        const float4* xp = (const float4*)(X + (size_t)j * FIN);
        #pragma unroll
        for (int q = 0; q < FOBS / 4; q++) ((float4*)xj)[q] = xp[q];

        #pragma unroll
        for (int ii = 0; ii < TIA; ii++) {
            float l = 0.f;
            #pragma unroll
            for (int k = 0; k < FOBS; k++)
                l = fmaf(fabsf(sh[ii][k] - xj[k]), sa[k], l);
            int i = i0 + ii;
            float u = gum[(size_t)i * NN_ + j];
            float t = EPSF - flog(u + EPSF);
            float t2 = t * t, t4 = t2 * t2, t8 = t4 * t4;
            float w = fexp(-10.f * l) * (t8 * t2);
            w = fminf(w, 1e30f);
            float A = frcp(1.0f + w);
            if (j == i) A = 1.0f;
            Ap[(size_t)i * NN_ + j] = A;
        }
    }
}

// ---------------- small per-hop kernels ----------------
__global__ void k_cvec(const float* __restrict__ Wq, const float* __restrict__ Wv,
                       const float* __restrict__ a, int F) {
    int t = threadIdx.x;
    if (t < F) {
        float s1 = 0.f, s2 = 0.f;
        for (int g = 0; g < G_; g++) {
            s1 = fmaf(Wq[t * G_ + g], a[g], s1);
            s2 = fmaf(Wv[t * G_ + g], a[G_ + g], s2);
        }
        g_cq[t] = s1; g_cv[t] = s2;
    }
}

__global__ __launch_bounds__(256) void k_wvec(const float* __restrict__ Xp, int hop, int F) {
    const float* H = hop ? g_H : Xp;
    int row  = blockIdx.x * 8 + (threadIdx.x >> 5);
    int lane = threadIdx.x & 31;
    float s1 = 0.f, s2 = 0.f;
    for (int f = lane; f < F; f += 32) {
        float h = H[(size_t)row * F + f];
        s1 = fmaf(h, g_cq[f], s1);
        s2 = fmaf(h, g_cv[f], s2);
    }
    #pragma unroll
    for (int o = 16; o; o >>= 1) {
        s1 += __shfl_xor_sync(0xFFFFFFFFu, s1, o);
        s2 += __shfl_xor_sync(0xFFFFFFFFu, s2, o);
    }
    if (lane == 0) { g_w1[row] = s1; g_w2[row] = s2; }
}

// Wh = H @ Ws in bf16 [j][g]. Block: 32 rows x 128 cols, 256 threads, 64 blocks.
__global__ __launch_bounds__(256) void k_wh(const float* __restrict__ Xp,
                                            const float* __restrict__ Ws,
                                            int hop, int F) {
    const float* H = hop ? g_H : Xp;
    __shared__ float sH[32][36];
    __shared__ float sWs[32][132];
    int tid = threadIdx.x;
    int i0 = blockIdx.x * 32;
    int rp = tid >> 3;        // row 0..31
    int cg = tid & 7;         // col group: cg*16..+15
    float acc[16];
    #pragma unroll
    for (int c = 0; c < 16; c++) acc[c] = 0.f;

    for (int fc = 0; fc < F / 32; fc++) {
        __syncthreads();
        // load H tile 32x32 (256 float4)
        {
            int q = tid;
            int rr = q >> 3, c4 = q & 7;
            *(float4*)&sH[rr][c4 * 4] = *(const float4*)&H[(size_t)(i0 + rr) * F + fc * 32 + c4 * 4];
        }
        // load Ws tile 32x128 (1024 float4)
        #pragma unroll
        for (int p = 0; p < 4; p++) {
            int q = p * 256 + tid;
            int fr = q >> 5, c4 = q & 31;
            *(float4*)&sWs[fr][c4 * 4] = *(const float4*)&Ws[(size_t)(fc * 32 + fr) * G_ + c4 * 4];
        }
        __syncthreads();
        #pragma unroll
        for (int ff = 0; ff < 32; ff++) {
            float h0 = sH[rp][ff];
            const float* wr = &sWs[ff][cg * 16];
            #pragma unroll
            for (int c = 0; c < 16; c++)
                acc[c] = fmaf(h0, wr[c], acc[c]);
        }
    }
    #pragma unroll
    for (int c = 0; c < 16; c += 2) {
        __nv_bfloat162 bb = __floats2bfloat162_rn(acc[c], acc[c + 1]);
        *(__nv_bfloat162*)&g_Whb[(size_t)(i0 + rp) * G_ + cg * 16 + c] = bb;
    }
}

// row max of masked e (block per row)
__global__ __launch_bounds__(256) void k_max(const float* __restrict__ Ap) {
    __shared__ float red[8];
    int i = blockIdx.x, tid = threadIdx.x;
    float w1 = g_w1[i];
    const float4* ar = (const float4*)(Ap + (size_t)i * NN_);
    const float4* wr = (const float4*)g_w2;
    float m = -3.4e38f;
    #pragma unroll
    for (int q = 0; q < 2; q++) {
        int c4 = tid * 2 + q;
        float4 a = ar[c4];
        float4 w = wr[c4];
        float av[4] = {a.x, a.y, a.z, a.w};
        float wv[4] = {w.x, w.y, w.z, w.w};
        #pragma unroll
        for (int e = 0; e < 4; e++) {
            if (av[e] > 0.01f) {
                float ev = w1 * wv[e];
                ev = ev > 0.f ? ev : 0.2f * ev;
                m = fmaxf(m, ev);
            }
        }
    }
    #pragma unroll
    for (int o = 16; o; o >>= 1) m = fmaxf(m, __shfl_xor_sync(0xFFFFFFFFu, m, o));
    if ((tid & 31) == 0) red[tid >> 5] = m;
    __syncthreads();
    if (tid < 32) {
        float v = (tid < 8) ? red[tid] : -3.4e38f;
        #pragma unroll
        for (int o = 4; o; o >>= 1) v = fmaxf(v, __shfl_xor_sync(0xFFFFFFFFu, v, o));
        if (tid == 0) g_m[i] = v;
    }
}

// ---------------- fused P-generation + mma.sync GEMM ----------------
// grid (16, JSPLIT), 256 threads (8 warps as 2m x 4n), out tile 128x128
__global__ __launch_bounds__(256) void k_attn_mma(const float* __restrict__ Ap) {
    __shared__ __nv_bfloat16 sA[MT][SAP];       // P chunk  128 x 32
    __shared__ __nv_bfloat16 sB[KC][SBP];       // Wh chunk  32 x 128

    int tid = threadIdx.x, wid = tid >> 5, lane = tid & 31;
    int i0 = blockIdx.x * MT;
    int js = blockIdx.y;
    int wm = wid >> 2, wn = wid & 3;            // warp tile: rows wm*64, cols wn*32

    uint32_t SAb = smem_u32(sA), SBb = smem_u32(sB);

    int r = tid >> 1, h = tid & 1;              // P-gen: row r, 16 cols at h*16
    float w1r = g_w1[i0 + r], mr = g_m[i0 + r];
    float zp = 0.f;

    float acc[4][4][4];
    #pragma unroll
    for (int mi = 0; mi < 4; mi++)
        #pragma unroll
        for (int ni = 0; ni < 4; ni++)
            #pragma unroll
            for (int q = 0; q < 4; q++) acc[mi][ni][q] = 0.f;

    // ldmatrix base addresses (row stride 80B, 16B-aligned)
    uint32_t aBase = SAb + (uint32_t)(wm * 64 + (lane & 15)) * (SAP * 2) + (uint32_t)((lane >> 4) * 16);
    uint32_t bBase = SBb + (uint32_t)(lane & 15) * (SBP * 2) + (uint32_t)(wn * 64);

    for (int cc = 0; cc < NCH; cc++) {
        int j0 = js * KSPAN + cc * KC;
        __syncthreads();    // previous chunk's mma done before overwrite
        // ---- load Wh chunk 32 x 128 bf16 (2 passes: full 32 rows) ----
        #pragma unroll
        for (int ps = 0; ps < 2; ps++) {
            int idx = ps * 256 + tid;
            int row = idx >> 4, c16 = idx & 15;
            uint4 v = *(const uint4*)&g_Whb[(size_t)(j0 + row) * G_ + c16 * 8];
            sts128(SBb + (uint32_t)row * (SBP * 2) + (uint32_t)c16 * 16, v.x, v.y, v.z, v.w);
        }
        // ---- compute P chunk: row r, cols h*16..+15 ----
        {
            const float* arow = Ap + (size_t)(i0 + r) * NN_ + j0 + h * 16;
            const float* w2p  = g_w2 + j0 + h * 16;
            uint32_t dst = SAb + (uint32_t)r * (SAP * 2) + (uint32_t)h * 32;
            #pragma unroll
            for (int c8 = 0; c8 < 2; c8++) {
                float4 a0 = ((const float4*)arow)[c8 * 2];
                float4 a1 = ((const float4*)arow)[c8 * 2 + 1];
                float4 b0 = ((const float4*)w2p)[c8 * 2];
                float4 b1 = ((const float4*)w2p)[c8 * 2 + 1];
                float av[8] = {a0.x, a0.y, a0.z, a0.w, a1.x, a1.y, a1.z, a1.w};
                float wv[8] = {b0.x, b0.y, b0.z, b0.w, b1.x, b1.y, b1.z, b1.w};
                float pv[8];
                #pragma unroll
                for (int q = 0; q < 8; q++) {
                    float p = 0.f;
                    if (av[q] > 0.01f) {
                        float e = w1r * wv[q];
                        e = e > 0.f ? e : 0.2f * e;
                        p = fexp(e - mr);
                    }
                    pv[q] = p;
                }
                uint32_t pk[4];
                #pragma unroll
                for (int qq = 0; qq < 4; qq++) {
                    __nv_bfloat162 bb = __floats2bfloat162_rn(pv[2 * qq], pv[2 * qq + 1]);
                    pk[qq] = *reinterpret_cast<uint32_t*>(&bb);
                    float2 f2 = __bfloat1622float2(bb);
                    zp += f2.x + f2.y;
                }
                sts128(dst + c8 * 16, pk[0], pk[1], pk[2], pk[3]);
            }
        }
        __syncthreads();
        // ---- MMA: 2 k-steps of 16 ----
        #pragma unroll
        for (int ks = 0; ks < 2; ks++) {
            uint32_t afr[4][4];
            #pragma unroll
            for (int mi = 0; mi < 4; mi++)
                ldmA(afr[mi], aBase + (uint32_t)(mi * 16) * (SAP * 2) + (uint32_t)ks * 32);
            uint32_t bfr[4][2];
            #pragma unroll
            for (int ni = 0; ni < 4; ni++)
                ldmB(bfr[ni], bBase + (uint32_t)(ks * 16) * (SBP * 2) + (uint32_t)ni * 16);
            #pragma unroll
            for (int mi = 0; mi < 4; mi++)
                #pragma unroll
                for (int ni = 0; ni < 4; ni++)
                    mma16816(acc[mi][ni], afr[mi], bfr[ni]);
        }
    }

    // ---- epilogue: accumulators -> deterministic partials ----
    #pragma unroll
    for (int mi = 0; mi < 4; mi++) {
        int row0 = i0 + wm * 64 + mi * 16 + (lane >> 2);
        #pragma unroll
        for (int ni = 0; ni < 4; ni++) {
            int col = wn * 32 + ni * 8 + (lane & 3) * 2;
            *(float2*)&g_part[js][(size_t)row0 * G_ + col] =
                make_float2(acc[mi][ni][0], acc[mi][ni][1]);
            *(float2*)&g_part[js][(size_t)(row0 + 8) * G_ + col] =
                make_float2(acc[mi][ni][2], acc[mi][ni][3]);
        }
    }
    zp += __shfl_xor_sync(0xFFFFFFFFu, zp, 1);
    if (h == 0) g_Zpart[js][i0 + r] = zp;
}

// H = relu(sum partials / sum Z)
__global__ __launch_bounds__(256) void k_epi(float* __restrict__ dst, int toGlobal) {
    int idx = blockIdx.x * 256 + threadIdx.x;
    int i = idx >> 7;
    float s = 0.f, z = 0.f;
    #pragma unroll
    for (int t = 0; t < JSPLIT; t++) { s += g_part[t][idx]; z += g_Zpart[t][i]; }
    float h = s * frcp(z);
    h = h > 0.f ? h : 0.f;
    if (toGlobal) g_H[idx] = h; else dst[idx] = h;
}

// ---------------- launcher ----------------
extern "C" void kernel_launch(void* const* d_in, const int* in_sizes, int n_in,
                              void* d_out, int out_size) {
    const float* X    = (const float*)d_in[0];
    const float* gum  = (const float*)d_in[1];
    const float* alnk = (const float*)d_in[2];
    const float* Ws[2] = { (const float*)d_in[3], (const float*)d_in[4] };
    const float* Wq[2] = { (const float*)d_in[5], (const float*)d_in[6] };
    const float* Wv[2] = { (const float*)d_in[7], (const float*)d_in[8] };
    const float* aa[2] = { (const float*)d_in[9], (const float*)d_in[10] };
    float* out = (float*)d_out;

    float* Ap;
    if (out_size >= NG + NSQ) Ap = out + NG;
    else cudaGetSymbolAddress((void**)&Ap, g_Afb);

    k_A<<<NN_ / TIA, 256>>>(X, gum, alnk, Ap);

    for (int k = 0; k < 2; k++) {
        int F = (k == 0) ? FIN : G_;
        k_cvec<<<1, 128>>>(Wq[k], Wv[k], aa[k], F);
        k_wvec<<<NN_ / 8, 256>>>(X, k, F);
        k_wh<<<NN_ / 32, 256>>>(X, Ws[k], k, F);
        k_max<<<NN_, 256>>>(Ap);
        dim3 ag(NN_ / MT, JSPLIT);
        k_attn_mma<<<ag, 256>>>(Ap);
        k_epi<<<NG / 256, 256>>>(out, k == 0 ? 1 : 0);
    }

    if (out_size >= NG + NSQ + NN_ * FIN)
        cudaMemcpyAsync(out + NG + NSQ, X, (size_t)NN_ * FIN * sizeof(float),
                        cudaMemcpyDeviceToDevice, 0);
}

// round 6
// speedup vs baseline: 1.3868x; 1.2273x over previous
#include <cuda_runtime.h>
#include <cuda_fp16.h>
#include <cstdint>

#define NN_ 2048
#define FIN 64
#define G_ 128
#define FOBS 32
#define NG (NN_*G_)
#define NSQ (NN_*NN_)
#define EPSF 1e-10f
#define TIA 8

#define MT 128
#define JSPLIT 8
#define KSPAN (NN_/JSPLIT)   // 256 j per block
#define KC 32                // j chunk
#define NCH (KSPAN/KC)       // 8

// SMEM padded strides (fp16 elems). Row strides are 16B multiples:
// SAP=40 -> 80B (conflict-free ldmatrix), SBP=136 -> 272B
#define SAP 40
#define SBP 136

// ---------------- scratch (static device, no allocs) ----------------
__device__ float g_Afb[NSQ];
__device__ float g_H[NG];
__device__ __half g_Whb[NG];                  // Wh fp16, [j][g] row-major
__device__ uint32_t g_mask[NN_][64];          // A>0.01 bitmask
__device__ float g_w1[NN_], g_w2[NN_], g_m[NN_];
__device__ float g_cq[G_], g_cv[G_];
__device__ float g_part[JSPLIT][NG];
__device__ float g_Zpart[JSPLIT][NN_];

// ---------------- FMA-pipe math (no MUFU) ----------------
__device__ __forceinline__ float fexp(float x) {
    float x2 = x * 1.4426950408889634f;
    x2 = fminf(fmaxf(x2, -126.0f), 126.0f);
    float r = x2 + 12582912.0f;
    int   n = __float_as_int(r) - 0x4B400000;
    float f = x2 - (r - 12582912.0f);
    float p = 1.5403512e-4f;
    p = fmaf(p, f, 1.33335574e-3f);
    p = fmaf(p, f, 9.61812911e-3f);
    p = fmaf(p, f, 5.55041087e-2f);
    p = fmaf(p, f, 2.40226507e-1f);
    p = fmaf(p, f, 6.93147181e-1f);
    p = fmaf(p, f, 1.0f);
    return p * __int_as_float((n + 127) << 23);
}

__device__ __forceinline__ float flog(float x) {
    int ix = __float_as_int(x);
    int e  = (ix >> 23) - 127;
    float m = __int_as_float((ix & 0x007FFFFF) | 0x3F800000);
    if (m > 1.41421356f) { m *= 0.5f; e += 1; }
    float f = m - 1.0f;
    float p = -0.1f;
    p = fmaf(p, f,  0.111111111f);
    p = fmaf(p, f, -0.125f);
    p = fmaf(p, f,  0.142857143f);
    p = fmaf(p, f, -0.166666667f);
    p = fmaf(p, f,  0.2f);
    p = fmaf(p, f, -0.25f);
    p = fmaf(p, f,  0.333333333f);
    p = fmaf(p, f, -0.5f);
    p = fmaf(p, f,  1.0f);
    p = p * f;
    return fmaf((float)e, 0.69314718056f, p);
}

__device__ __forceinline__ float frcp(float d) {
    float y = __int_as_float(0x7EF311C3 - __float_as_int(d));
    y = y * (2.0f - d * y);
    y = y * (2.0f - d * y);
    y = y * (2.0f - d * y);
    return y;
}

// ---------------- base-ISA tensor-core helpers ----------------
__device__ __forceinline__ uint32_t smem_u32(const void* p) {
    uint32_t a;
    asm("{ .reg .u64 t; cvta.to.shared.u64 t, %1; cvt.u32.u64 %0, t; }" : "=r"(a) : "l"(p));
    return a;
}
__device__ __forceinline__ void ldmA(uint32_t* a, uint32_t addr) {
    asm volatile("ldmatrix.sync.aligned.m8n8.x4.shared.b16 {%0,%1,%2,%3}, [%4];"
                 : "=r"(a[0]), "=r"(a[1]), "=r"(a[2]), "=r"(a[3]) : "r"(addr));
}
__device__ __forceinline__ void ldmB(uint32_t* b, uint32_t addr) {
    asm volatile("ldmatrix.sync.aligned.m8n8.x2.trans.shared.b16 {%0,%1}, [%2];"
                 : "=r"(b[0]), "=r"(b[1]) : "r"(addr));
}
__device__ __forceinline__ void mma16816(float* d, const uint32_t* a, const uint32_t* b) {
    asm volatile("mma.sync.aligned.m16n8k16.row.col.f32.f16.f16.f32 "
                 "{%0,%1,%2,%3}, {%4,%5,%6,%7}, {%8,%9}, {%0,%1,%2,%3};"
                 : "+f"(d[0]), "+f"(d[1]), "+f"(d[2]), "+f"(d[3])
                 : "r"(a[0]), "r"(a[1]), "r"(a[2]), "r"(a[3]), "r"(b[0]), "r"(b[1]));
}
__device__ __forceinline__ void sts128(uint32_t addr, uint32_t r0, uint32_t r1, uint32_t r2, uint32_t r3) {
    asm volatile("st.shared.v4.b32 [%0], {%1,%2,%3,%4};"
                 :: "r"(addr), "r"(r0), "r"(r1), "r"(r2), "r"(r3) : "memory");
}
__device__ __forceinline__ uint32_t h2u(float a, float b) {
    __half2 h = __floats2half2_rn(a, b);
    return *reinterpret_cast<uint32_t*>(&h);
}

// ---------------- Kernel 1: A matrix + mask ----------------
__global__ __launch_bounds__(256) void k_A(const float* __restrict__ X,
                                           const float* __restrict__ gum,
                                           const float* __restrict__ alink,
                                           float* __restrict__ Ap) {
    __shared__ float sh[TIA][FOBS];
    __shared__ float sa[FOBS];
    int tid = threadIdx.x;
    int i0  = blockIdx.x * TIA;
    if (tid < FOBS) sa[tid] = alink[tid];
    sh[tid >> 5][tid & 31] = X[(i0 + (tid >> 5)) * FIN + (tid & 31)];
    __syncthreads();

    for (int l = 0; l < NN_ / 256; l++) {
        int j = l * 256 + tid;
        float xj[FOBS];
        const float4* xp = (const float4*)(X + (size_t)j * FIN);
        #pragma unroll
        for (int q = 0; q < FOBS / 4; q++) ((float4*)xj)[q] = xp[q];

        #pragma unroll
        for (int ii = 0; ii < TIA; ii++) {
            float lgt = 0.f;
            #pragma unroll
            for (int k = 0; k < FOBS; k++)
                lgt = fmaf(fabsf(sh[ii][k] - xj[k]), sa[k], lgt);
            int i = i0 + ii;
            float u = gum[(size_t)i * NN_ + j];
            float t = EPSF - flog(u + EPSF);
            float t2 = t * t, t4 = t2 * t2, t8 = t4 * t4;
            float w = fexp(-10.f * lgt) * (t8 * t2);
            w = fminf(w, 1e30f);
            float A = frcp(1.0f + w);
            if (j == i) A = 1.0f;
            Ap[(size_t)i * NN_ + j] = A;
            uint32_t bal = __ballot_sync(0xFFFFFFFFu, A > 0.01f);
            if ((tid & 31) == 0) g_mask[i][(j >> 5)] = bal;
        }
    }
}

// ---------------- small per-hop kernels ----------------
__global__ void k_cvec(const float* __restrict__ Wq, const float* __restrict__ Wv,
                       const float* __restrict__ a, int F) {
    int t = threadIdx.x;
    if (t < F) {
        float s1 = 0.f, s2 = 0.f;
        for (int g = 0; g < G_; g++) {
            s1 = fmaf(Wq[t * G_ + g], a[g], s1);
            s2 = fmaf(Wv[t * G_ + g], a[G_ + g], s2);
        }
        g_cq[t] = s1; g_cv[t] = s2;
    }
}

__global__ __launch_bounds__(256) void k_wvec(const float* __restrict__ Xp, int hop, int F) {
    const float* H = hop ? g_H : Xp;
    int row  = blockIdx.x * 8 + (threadIdx.x >> 5);
    int lane = threadIdx.x & 31;
    float s1 = 0.f, s2 = 0.f;
    for (int f = lane; f < F; f += 32) {
        float h = H[(size_t)row * F + f];
        s1 = fmaf(h, g_cq[f], s1);
        s2 = fmaf(h, g_cv[f], s2);
    }
    #pragma unroll
    for (int o = 16; o; o >>= 1) {
        s1 += __shfl_xor_sync(0xFFFFFFFFu, s1, o);
        s2 += __shfl_xor_sync(0xFFFFFFFFu, s2, o);
    }
    if (lane == 0) { g_w1[row] = s1; g_w2[row] = s2; }
}

// row max of masked e via monotone transform of masked max/min of w2
__global__ __launch_bounds__(256) void k_mm() {
    int row  = blockIdx.x * 8 + (threadIdx.x >> 5);
    int lane = threadIdx.x & 31;
    uint32_t wa = g_mask[row][lane];
    uint32_t wb = g_mask[row][lane + 32];
    const float* w2a = g_w2 + lane * 32;
    const float* w2b = g_w2 + (lane + 32) * 32;
    float mx = -3.4e38f, mn = 3.4e38f;
    #pragma unroll
    for (int k = 0; k < 32; k++) {
        if ((wa >> k) & 1u) { float v = w2a[k]; mx = fmaxf(mx, v); mn = fminf(mn, v); }
        if ((wb >> k) & 1u) { float v = w2b[k]; mx = fmaxf(mx, v); mn = fminf(mn, v); }
    }
    #pragma unroll
    for (int o = 16; o; o >>= 1) {
        mx = fmaxf(mx, __shfl_xor_sync(0xFFFFFFFFu, mx, o));
        mn = fminf(mn, __shfl_xor_sync(0xFFFFFFFFu, mn, o));
    }
    if (lane == 0) {
        float w1 = g_w1[row];
        float e = w1 * (w1 >= 0.f ? mx : mn);
        e = e > 0.f ? e : 0.2f * e;
        g_m[row] = e;
    }
}

// ---------------- Wh = H @ Ws via fp16 mma, output fp16 [j][g] ----------------
// grid 16 blocks, 256 threads (8 warps as 2m x 4n), out tile 128x128, K chunks of 16
__global__ __launch_bounds__(256) void k_wh(const float* __restrict__ Xp,
                                            const float* __restrict__ Ws,
                                            int hop, int F) {
    __shared__ __half sH[MT][SAP];
    __shared__ __half sW[16][SBP];
    const float* H = hop ? g_H : Xp;

    int tid = threadIdx.x, wid = tid >> 5, lane = tid & 31;
    int i0 = blockIdx.x * MT;
    int wm = wid >> 2, wn = wid & 3;

    uint32_t SHb = smem_u32(sH), SWb = smem_u32(sW);
    uint32_t aBase = SHb + (uint32_t)(wm * 64 + (lane & 15)) * (SAP * 2) + (uint32_t)((lane >> 4) * 16);
    uint32_t bBase = SWb + (uint32_t)(lane & 15) * (SBP * 2) + (uint32_t)(wn * 64);

    float acc[4][4][4];
    #pragma unroll
    for (int mi = 0; mi < 4; mi++)
        #pragma unroll
        for (int ni = 0; ni < 4; ni++)
            #pragma unroll
            for (int q = 0; q < 4; q++) acc[mi][ni][q] = 0.f;

    for (int f0 = 0; f0 < F; f0 += 16) {
        __syncthreads();
        // H tile 128x16 fp32 -> fp16
        {
            int row = tid >> 1, hh = tid & 1;
            const float* src = H + (size_t)(i0 + row) * F + f0 + hh * 8;
            float4 v0 = *(const float4*)src;
            float4 v1 = *(const float4*)(src + 4);
            sts128(SHb + (uint32_t)row * (SAP * 2) + (uint32_t)hh * 16,
                   h2u(v0.x, v0.y), h2u(v0.z, v0.w), h2u(v1.x, v1.y), h2u(v1.z, v1.w));
        }
        // Ws tile 16x128 fp32 -> fp16
        {
            int fr = tid >> 4, seg = tid & 15;
            const float* src = Ws + (size_t)(f0 + fr) * G_ + seg * 8;
            float4 v0 = *(const float4*)src;
            float4 v1 = *(const float4*)(src + 4);
            sts128(SWb + (uint32_t)fr * (SBP * 2) + (uint32_t)seg * 16,
                   h2u(v0.x, v0.y), h2u(v0.z, v0.w), h2u(v1.x, v1.y), h2u(v1.z, v1.w));
        }
        __syncthreads();
        uint32_t afr[4][4];
        #pragma unroll
        for (int mi = 0; mi < 4; mi++)
            ldmA(afr[mi], aBase + (uint32_t)(mi * 16) * (SAP * 2));
        uint32_t bfr[4][2];
        #pragma unroll
        for (int ni = 0; ni < 4; ni++)
            ldmB(bfr[ni], bBase + (uint32_t)ni * 16);
        #pragma unroll
        for (int mi = 0; mi < 4; mi++)
            #pragma unroll
            for (int ni = 0; ni < 4; ni++)
                mma16816(acc[mi][ni], afr[mi], bfr[ni]);
    }

    #pragma unroll
    for (int mi = 0; mi < 4; mi++) {
        int row0 = i0 + wm * 64 + mi * 16 + (lane >> 2);
        #pragma unroll
        for (int ni = 0; ni < 4; ni++) {
            int col = wn * 32 + ni * 8 + (lane & 3) * 2;
            __half2 h0 = __floats2half2_rn(acc[mi][ni][0], acc[mi][ni][1]);
            __half2 h1 = __floats2half2_rn(acc[mi][ni][2], acc[mi][ni][3]);
            *(__half2*)&g_Whb[(size_t)row0 * G_ + col] = h0;
            *(__half2*)&g_Whb[(size_t)(row0 + 8) * G_ + col] = h1;
        }
    }
}

// ---------------- fused P-generation + fp16 mma GEMM ----------------
// grid (16, JSPLIT), 256 threads (8 warps as 2m x 4n), out tile 128x128
__global__ __launch_bounds__(256) void k_attn_mma() {
    __shared__ __half sA[MT][SAP];       // P chunk  128 x 32
    __shared__ __half sB[KC][SBP];       // Wh chunk  32 x 128

    int tid = threadIdx.x, wid = tid >> 5, lane = tid & 31;
    int i0 = blockIdx.x * MT;
    int js = blockIdx.y;
    int wm = wid >> 2, wn = wid & 3;

    uint32_t SAb = smem_u32(sA), SBb = smem_u32(sB);

    int r = tid >> 1, h = tid & 1;              // P-gen: row r, 16 cols at h*16
    float w1r = g_w1[i0 + r], mr = g_m[i0 + r];
    float zp = 0.f;

    float acc[4][4][4];
    #pragma unroll
    for (int mi = 0; mi < 4; mi++)
        #pragma unroll
        for (int ni = 0; ni < 4; ni++)
            #pragma unroll
            for (int q = 0; q < 4; q++) acc[mi][ni][q] = 0.f;

    uint32_t aBase = SAb + (uint32_t)(wm * 64 + (lane & 15)) * (SAP * 2) + (uint32_t)((lane >> 4) * 16);
    uint32_t bBase = SBb + (uint32_t)(lane & 15) * (SBP * 2) + (uint32_t)(wn * 64);

    for (int cc = 0; cc < NCH; cc++) {
        int j0 = js * KSPAN + cc * KC;
        __syncthreads();
        // ---- Wh chunk 32x128 fp16 (2 passes) ----
        #pragma unroll
        for (int ps = 0; ps < 2; ps++) {
            int idx = ps * 256 + tid;
            int row = idx >> 4, c16 = idx & 15;
            uint4 v = *(const uint4*)&g_Whb[(size_t)(j0 + row) * G_ + c16 * 8];
            sts128(SBb + (uint32_t)row * (SBP * 2) + (uint32_t)c16 * 16, v.x, v.y, v.z, v.w);
        }
        // ---- P chunk: row r, cols h*16..+15, mask-driven ----
        {
            uint32_t mword = g_mask[i0 + r][js * 8 + cc];
            uint32_t mh = (mword >> (h * 16)) & 0xFFFFu;
            const float* w2p = g_w2 + j0 + h * 16;
            uint32_t dst = SAb + (uint32_t)r * (SAP * 2) + (uint32_t)h * 32;
            #pragma unroll
            for (int c8 = 0; c8 < 2; c8++) {
                uint32_t m8 = (mh >> (c8 * 8)) & 0xFFu;
                float4 b0 = ((const float4*)w2p)[c8 * 2];
                float4 b1 = ((const float4*)w2p)[c8 * 2 + 1];
                float wv[8] = {b0.x, b0.y, b0.z, b0.w, b1.x, b1.y, b1.z, b1.w};
                float pv[8];
                #pragma unroll
                for (int q = 0; q < 8; q++) {
                    float p = 0.f;
                    if ((m8 >> q) & 1u) {
                        float e = w1r * wv[q];
                        e = e > 0.f ? e : 0.2f * e;
                        p = fexp(e - mr);
                    }
                    pv[q] = p;
                }
                uint32_t pk[4];
                #pragma unroll
                for (int qq = 0; qq < 4; qq++) {
                    __half2 hh = __floats2half2_rn(pv[2 * qq], pv[2 * qq + 1]);
                    pk[qq] = *reinterpret_cast<uint32_t*>(&hh);
                    float2 f2 = __half22float2(hh);
                    zp += f2.x + f2.y;
                }
                sts128(dst + c8 * 16, pk[0], pk[1], pk[2], pk[3]);
            }
        }
        __syncthreads();
        // ---- MMA: 2 k-steps of 16 ----
        #pragma unroll
        for (int ks = 0; ks < 2; ks++) {
            uint32_t afr[4][4];
            #pragma unroll
            for (int mi = 0; mi < 4; mi++)
                ldmA(afr[mi], aBase + (uint32_t)(mi * 16) * (SAP * 2) + (uint32_t)ks * 32);
            uint32_t bfr[4][2];
            #pragma unroll
            for (int ni = 0; ni < 4; ni++)
                ldmB(bfr[ni], bBase + (uint32_t)(ks * 16) * (SBP * 2) + (uint32_t)ni * 16);
            #pragma unroll
            for (int mi = 0; mi < 4; mi++)
                #pragma unroll
                for (int ni = 0; ni < 4; ni++)
                    mma16816(acc[mi][ni], afr[mi], bfr[ni]);
        }
    }

    // ---- epilogue: deterministic partials ----
    #pragma unroll
    for (int mi = 0; mi < 4; mi++) {
        int row0 = i0 + wm * 64 + mi * 16 + (lane >> 2);
        #pragma unroll
        for (int ni = 0; ni < 4; ni++) {
            int col = wn * 32 + ni * 8 + (lane & 3) * 2;
            *(float2*)&g_part[js][(size_t)row0 * G_ + col] =
                make_float2(acc[mi][ni][0], acc[mi][ni][1]);
            *(float2*)&g_part[js][(size_t)(row0 + 8) * G_ + col] =
                make_float2(acc[mi][ni][2], acc[mi][ni][3]);
        }
    }
    zp += __shfl_xor_sync(0xFFFFFFFFu, zp, 1);
    if (h == 0) g_Zpart[js][i0 + r] = zp;
}

// H = relu(sum partials / sum Z)
__global__ __launch_bounds__(256) void k_epi(float* __restrict__ dst, int toGlobal) {
    int idx = blockIdx.x * 256 + threadIdx.x;
    int i = idx >> 7;
    float s = 0.f, z = 0.f;
    #pragma unroll
    for (int t = 0; t < JSPLIT; t++) { s += g_part[t][idx]; z += g_Zpart[t][i]; }
    float h = s * frcp(z);
    h = h > 0.f ? h : 0.f;
    if (toGlobal) g_H[idx] = h; else dst[idx] = h;
}

// ---------------- launcher ----------------
extern "C" void kernel_launch(void* const* d_in, const int* in_sizes, int n_in,
                              void* d_out, int out_size) {
    const float* X    = (const float*)d_in[0];
    const float* gum  = (const float*)d_in[1];
    const float* alnk = (const float*)d_in[2];
    const float* Ws[2] = { (const float*)d_in[3], (const float*)d_in[4] };
    const float* Wq[2] = { (const float*)d_in[5], (const float*)d_in[6] };
    const float* Wv[2] = { (const float*)d_in[7], (const float*)d_in[8] };
    const float* aa[2] = { (const float*)d_in[9], (const float*)d_in[10] };
    float* out = (float*)d_out;

    float* Ap;
    if (out_size >= NG + NSQ) Ap = out + NG;
    else cudaGetSymbolAddress((void**)&Ap, g_Afb);

    k_A<<<NN_ / TIA, 256>>>(X, gum, alnk, Ap);

    for (int k = 0; k < 2; k++) {
        int F = (k == 0) ? FIN : G_;
        k_cvec<<<1, 128>>>(Wq[k], Wv[k], aa[k], F);
        k_wvec<<<NN_ / 8, 256>>>(X, k, F);
        k_mm<<<NN_ / 8, 256>>>();
        k_wh<<<NN_ / MT, 256>>>(X, Ws[k], k, F);
        dim3 ag(NN_ / MT, JSPLIT);
        k_attn_mma<<<ag, 256>>>();
        k_epi<<<NG / 256, 256>>>(out, k == 0 ? 1 : 0);
    }

    if (out_size >= NG + NSQ + NN_ * FIN)
        cudaMemcpyAsync(out + NG + NSQ, X, (size_t)NN_ * FIN * sizeof(float),
                        cudaMemcpyDeviceToDevice, 0);
}

// round 8
// speedup vs baseline: 1.6086x; 1.1599x over previous
#include <cuda_runtime.h>
#include <cuda_fp16.h>
#include <cstdint>

#define NN_ 2048
#define FIN 64
#define G_ 128
#define FOBS 32
#define NG (NN_*G_)
#define NSQ (NN_*NN_)
#define EPSF 1e-10f
#define TIA 8

#define MT 128
#define JSPLIT 8
#define KSPAN (NN_/JSPLIT)   // 256 j per block
#define KC 32                // j chunk
#define NCH (KSPAN/KC)       // 8

// SMEM padded strides (fp16 elems). Row strides are 16B multiples:
// SAP=40 -> 80B (conflict-free ldmatrix), SBP=136 -> 272B
#define SAP 40
#define SBP 136

// ---------------- scratch (static device, no allocs) ----------------
__device__ float g_Afb[NSQ];
__device__ float g_H[NG];
__device__ __half g_Whb[NG];                  // Wh fp16, [j][g] row-major
__device__ uint32_t g_mask[NN_][64];          // A>0.01 bitmask
__device__ float g_w1[NN_], g_w2[NN_], g_m[NN_];
__device__ float g_cq[G_], g_cv[G_];
__device__ float g_part[JSPLIT][NG];
__device__ float g_Zpart[JSPLIT][NN_];

// ---------------- FMA-pipe math (no MUFU) ----------------
__device__ __forceinline__ float fexp(float x) {
    float x2 = x * 1.4426950408889634f;
    x2 = fminf(fmaxf(x2, -126.0f), 126.0f);
    float r = x2 + 12582912.0f;
    int   n = __float_as_int(r) - 0x4B400000;
    float f = x2 - (r - 12582912.0f);
    float p = 1.5403512e-4f;
    p = fmaf(p, f, 1.33335574e-3f);
    p = fmaf(p, f, 9.61812911e-3f);
    p = fmaf(p, f, 5.55041087e-2f);
    p = fmaf(p, f, 2.40226507e-1f);
    p = fmaf(p, f, 6.93147181e-1f);
    p = fmaf(p, f, 1.0f);
    return p * __int_as_float((n + 127) << 23);
}

__device__ __forceinline__ float flog(float x) {
    int ix = __float_as_int(x);
    int e  = (ix >> 23) - 127;
    float m = __int_as_float((ix & 0x007FFFFF) | 0x3F800000);
    if (m > 1.41421356f) { m *= 0.5f; e += 1; }
    float f = m - 1.0f;
    float p = -0.1f;
    p = fmaf(p, f,  0.111111111f);
    p = fmaf(p, f, -0.125f);
    p = fmaf(p, f,  0.142857143f);
    p = fmaf(p, f, -0.166666667f);
    p = fmaf(p, f,  0.2f);
    p = fmaf(p, f, -0.25f);
    p = fmaf(p, f,  0.333333333f);
    p = fmaf(p, f, -0.5f);
    p = fmaf(p, f,  1.0f);
    p = p * f;
    return fmaf((float)e, 0.69314718056f, p);
}

__device__ __forceinline__ float frcp(float d) {
    float y = __int_as_float(0x7EF311C3 - __float_as_int(d));
    y = y * (2.0f - d * y);
    y = y * (2.0f - d * y);
    y = y * (2.0f - d * y);
    return y;
}

// ---------------- base-ISA tensor-core helpers ----------------
__device__ __forceinline__ uint32_t smem_u32(const void* p) {
    uint32_t a;
    asm("{ .reg .u64 t; cvta.to.shared.u64 t, %1; cvt.u32.u64 %0, t; }" : "=r"(a) : "l"(p));
    return a;
}
__device__ __forceinline__ void ldmA(uint32_t* a, uint32_t addr) {
    asm volatile("ldmatrix.sync.aligned.m8n8.x4.shared.b16 {%0,%1,%2,%3}, [%4];"
                 : "=r"(a[0]), "=r"(a[1]), "=r"(a[2]), "=r"(a[3]) : "r"(addr));
}
__device__ __forceinline__ void ldmB(uint32_t* b, uint32_t addr) {
    asm volatile("ldmatrix.sync.aligned.m8n8.x2.trans.shared.b16 {%0,%1}, [%2];"
                 : "=r"(b[0]), "=r"(b[1]) : "r"(addr));
}
__device__ __forceinline__ void mma16816(float* d, const uint32_t* a, const uint32_t* b) {
    asm volatile("mma.sync.aligned.m16n8k16.row.col.f32.f16.f16.f32 "
                 "{%0,%1,%2,%3}, {%4,%5,%6,%7}, {%8,%9}, {%0,%1,%2,%3};"
                 : "+f"(d[0]), "+f"(d[1]), "+f"(d[2]), "+f"(d[3])
                 : "r"(a[0]), "r"(a[1]), "r"(a[2]), "r"(a[3]), "r"(b[0]), "r"(b[1]));
}
__device__ __forceinline__ void sts128(uint32_t addr, uint32_t r0, uint32_t r1, uint32_t r2, uint32_t r3) {
    asm volatile("st.shared.v4.b32 [%0], {%1,%2,%3,%4};"
                 :: "r"(addr), "r"(r0), "r"(r1), "r"(r2), "r"(r3) : "memory");
}
__device__ __forceinline__ uint32_t h2u(float a, float b) {
    __half2 h = __floats2half2_rn(a, b);
    return *reinterpret_cast<uint32_t*>(&h);
}

// ---------------- Kernel 1: A matrix + mask ----------------
__global__ __launch_bounds__(256) void k_A(const float* __restrict__ X,
                                           const float* __restrict__ gum,
                                           const float* __restrict__ alink,
                                           float* __restrict__ Ap) {
    __shared__ float sh[TIA][FOBS];
    __shared__ float sa[FOBS];
    int tid = threadIdx.x;
    int i0  = blockIdx.x * TIA;
    if (tid < FOBS) sa[tid] = alink[tid];
    sh[tid >> 5][tid & 31] = X[(i0 + (tid >> 5)) * FIN + (tid & 31)];
    __syncthreads();

    for (int l = 0; l < NN_ / 256; l++) {
        int j = l * 256 + tid;
        float xj[FOBS];
        const float4* xp = (const float4*)(X + (size_t)j * FIN);
        #pragma unroll
        for (int q = 0; q < FOBS / 4; q++) ((float4*)xj)[q] = xp[q];

        #pragma unroll
        for (int ii = 0; ii < TIA; ii++) {
            float lgt = 0.f;
            #pragma unroll
            for (int k = 0; k < FOBS; k++)
                lgt = fmaf(fabsf(sh[ii][k] - xj[k]), sa[k], lgt);
            int i = i0 + ii;
            float u = gum[(size_t)i * NN_ + j];
            float t = EPSF - flog(u + EPSF);
            float t2 = t * t, t4 = t2 * t2, t8 = t4 * t4;
            float w = fexp(-10.f * lgt) * (t8 * t2);
            w = fminf(w, 1e30f);
            float A = frcp(1.0f + w);
            if (j == i) A = 1.0f;
            Ap[(size_t)i * NN_ + j] = A;
            uint32_t bal = __ballot_sync(0xFFFFFFFFu, A > 0.01f);
            if ((tid & 31) == 0) g_mask[i][(j >> 5)] = bal;
        }
    }
}

// ---------------- small per-hop kernels ----------------
__global__ void k_cvec(const float* __restrict__ Wq, const float* __restrict__ Wv,
                       const float* __restrict__ a, int F) {
    int t = threadIdx.x;
    if (t < F) {
        float s1 = 0.f, s2 = 0.f;
        for (int g = 0; g < G_; g++) {
            s1 = fmaf(Wq[t * G_ + g], a[g], s1);
            s2 = fmaf(Wv[t * G_ + g], a[G_ + g], s2);
        }
        g_cq[t] = s1; g_cv[t] = s2;
    }
}

__global__ __launch_bounds__(256) void k_wvec(const float* __restrict__ Xp, int hop, int F) {
    const float* H = hop ? g_H : Xp;
    int row  = blockIdx.x * 8 + (threadIdx.x >> 5);
    int lane = threadIdx.x & 31;
    float s1 = 0.f, s2 = 0.f;
    for (int f = lane; f < F; f += 32) {
        float h = H[(size_t)row * F + f];
        s1 = fmaf(h, g_cq[f], s1);
        s2 = fmaf(h, g_cv[f], s2);
    }
    #pragma unroll
    for (int o = 16; o; o >>= 1) {
        s1 += __shfl_xor_sync(0xFFFFFFFFu, s1, o);
        s2 += __shfl_xor_sync(0xFFFFFFFFu, s2, o);
    }
    if (lane == 0) { g_w1[row] = s1; g_w2[row] = s2; }
}

// row max of masked e: coalesced lane<->element mapping.
// lane L owns j = w*128 + L*4 + q (float4); mask word w*4 + (L>>3) via shfl broadcast.
__global__ __launch_bounds__(256) void k_mm() {
    int row  = blockIdx.x * 8 + (threadIdx.x >> 5);
    int lane = threadIdx.x & 31;
    uint32_t wa = g_mask[row][lane];        // words 0..31 (held lane-wise)
    uint32_t wb = g_mask[row][lane + 32];   // words 32..63
    int bsh = (lane & 7) * 4;               // bit offset of this lane's 4 elems
    float mx = -3.4e38f, mn = 3.4e38f;
    #pragma unroll
    for (int w = 0; w < 16; w++) {
        int widx = w * 4 + (lane >> 3);     // mask word index for this lane
        uint32_t word = (w < 8) ? __shfl_sync(0xFFFFFFFFu, wa, widx)
                                : __shfl_sync(0xFFFFFFFFu, wb, widx - 32);
        float4 v = *(const float4*)&g_w2[w * 128 + lane * 4];
        float vv[4] = {v.x, v.y, v.z, v.w};
        #pragma unroll
        for (int q = 0; q < 4; q++) {
            bool b = (word >> (bsh + q)) & 1u;
            float hi = b ? vv[q] : -3.4e38f;
            float lo = b ? vv[q] :  3.4e38f;
            mx = fmaxf(mx, hi);
            mn = fminf(mn, lo);
        }
    }
    #pragma unroll
    for (int o = 16; o; o >>= 1) {
        mx = fmaxf(mx, __shfl_xor_sync(0xFFFFFFFFu, mx, o));
        mn = fminf(mn, __shfl_xor_sync(0xFFFFFFFFu, mn, o));
    }
    if (lane == 0) {
        float w1 = g_w1[row];
        float e = w1 * (w1 >= 0.f ? mx : mn);
        e = e > 0.f ? e : 0.2f * e;
        g_m[row] = e;
    }
}

// ---------------- Wh = H @ Ws via fp16 mma, output fp16 [j][g] ----------------
// grid 16 blocks, 256 threads (8 warps as 2m x 4n), out tile 128x128, K chunks of 16
__global__ __launch_bounds__(256) void k_wh(const float* __restrict__ Xp,
                                            const float* __restrict__ Ws,
                                            int hop, int F) {
    __shared__ __half sH[MT][SAP];
    __shared__ __half sW[16][SBP];
    const float* H = hop ? g_H : Xp;

    int tid = threadIdx.x, wid = tid >> 5, lane = tid & 31;
    int i0 = blockIdx.x * MT;
    int wm = wid >> 2, wn = wid & 3;

    uint32_t SHb = smem_u32(sH), SWb = smem_u32(sW);
    uint32_t aBase = SHb + (uint32_t)(wm * 64 + (lane & 15)) * (SAP * 2) + (uint32_t)((lane >> 4) * 16);
    uint32_t bBase = SWb + (uint32_t)(lane & 15) * (SBP * 2) + (uint32_t)(wn * 64);

    float acc[4][4][4];
    #pragma unroll
    for (int mi = 0; mi < 4; mi++)
        #pragma unroll
        for (int ni = 0; ni < 4; ni++)
            #pragma unroll
            for (int q = 0; q < 4; q++) acc[mi][ni][q] = 0.f;

    for (int f0 = 0; f0 < F; f0 += 16) {
        __syncthreads();
        // H tile 128x16 fp32 -> fp16
        {
            int row = tid >> 1, hh = tid & 1;
            const float* src = H + (size_t)(i0 + row) * F + f0 + hh * 8;
            float4 v0 = *(const float4*)src;
            float4 v1 = *(const float4*)(src + 4);
            sts128(SHb + (uint32_t)row * (SAP * 2) + (uint32_t)hh * 16,
                   h2u(v0.x, v0.y), h2u(v0.z, v0.w), h2u(v1.x, v1.y), h2u(v1.z, v1.w));
        }
        // Ws tile 16x128 fp32 -> fp16
        {
            int fr = tid >> 4, seg = tid & 15;
            const float* src = Ws + (size_t)(f0 + fr) * G_ + seg * 8;
            float4 v0 = *(const float4*)src;
            float4 v1 = *(const float4*)(src + 4);
            sts128(SWb + (uint32_t)fr * (SBP * 2) + (uint32_t)seg * 16,
                   h2u(v0.x, v0.y), h2u(v0.z, v0.w), h2u(v1.x, v1.y), h2u(v1.z, v1.w));
        }
        __syncthreads();
        uint32_t afr[4][4];
        #pragma unroll
        for (int mi = 0; mi < 4; mi++)
            ldmA(afr[mi], aBase + (uint32_t)(mi * 16) * (SAP * 2));
        uint32_t bfr[4][2];
        #pragma unroll
        for (int ni = 0; ni < 4; ni++)
            ldmB(bfr[ni], bBase + (uint32_t)ni * 16);
        #pragma unroll
        for (int mi = 0; mi < 4; mi++)
            #pragma unroll
            for (int ni = 0; ni < 4; ni++)
                mma16816(acc[mi][ni], afr[mi], bfr[ni]);
    }

    #pragma unroll
    for (int mi = 0; mi < 4; mi++) {
        int row0 = i0 + wm * 64 + mi * 16 + (lane >> 2);
        #pragma unroll
        for (int ni = 0; ni < 4; ni++) {
            int col = wn * 32 + ni * 8 + (lane & 3) * 2;
            __half2 h0 = __floats2half2_rn(acc[mi][ni][0], acc[mi][ni][1]);
            __half2 h1 = __floats2half2_rn(acc[mi][ni][2], acc[mi][ni][3]);
            *(__half2*)&g_Whb[(size_t)row0 * G_ + col] = h0;
            *(__half2*)&g_Whb[(size_t)(row0 + 8) * G_ + col] = h1;
        }
    }
}

// ---------------- fused P-generation + fp16 mma GEMM ----------------
// grid (16, JSPLIT), 256 threads (8 warps as 2m x 4n), out tile 128x128
__global__ __launch_bounds__(256) void k_attn_mma() {
    __shared__ __half sA[MT][SAP];       // P chunk  128 x 32
    __shared__ __half sB[KC][SBP];       // Wh chunk  32 x 128

    int tid = threadIdx.x, wid = tid >> 5, lane = tid & 31;
    int i0 = blockIdx.x * MT;
    int js = blockIdx.y;
    int wm = wid >> 2, wn = wid & 3;

    uint32_t SAb = smem_u32(sA), SBb = smem_u32(sB);

    int r = tid >> 1, h = tid & 1;              // P-gen: row r, 16 cols at h*16
    float w1r = g_w1[i0 + r], mr = g_m[i0 + r];
    float zp = 0.f;

    float acc[4][4][4];
    #pragma unroll
    for (int mi = 0; mi < 4; mi++)
        #pragma unroll
        for (int ni = 0; ni < 4; ni++)
            #pragma unroll
            for (int q = 0; q < 4; q++) acc[mi][ni][q] = 0.f;

    uint32_t aBase = SAb + (uint32_t)(wm * 64 + (lane & 15)) * (SAP * 2) + (uint32_t)((lane >> 4) * 16);
    uint32_t bBase = SBb + (uint32_t)(lane & 15) * (SBP * 2) + (uint32_t)(wn * 64);

    for (int cc = 0; cc < NCH; cc++) {
        int j0 = js * KSPAN + cc * KC;
        __syncthreads();
        // ---- Wh chunk 32x128 fp16 (2 passes) ----
        #pragma unroll
        for (int ps = 0; ps < 2; ps++) {
            int idx = ps * 256 + tid;
            int row = idx >> 4, c16 = idx & 15;
            uint4 v = *(const uint4*)&g_Whb[(size_t)(j0 + row) * G_ + c16 * 8];
            sts128(SBb + (uint32_t)row * (SBP * 2) + (uint32_t)c16 * 16, v.x, v.y, v.z, v.w);
        }
        // ---- P chunk: row r, cols h*16..+15, mask-driven ----
        {
            uint32_t mword = g_mask[i0 + r][js * 8 + cc];
            uint32_t mh = (mword >> (h * 16)) & 0xFFFFu;
            const float* w2p = g_w2 + j0 + h * 16;
            uint32_t dst = SAb + (uint32_t)r * (SAP * 2) + (uint32_t)h * 32;
            #pragma unroll
            for (int c8 = 0; c8 < 2; c8++) {
                uint32_t m8 = (mh >> (c8 * 8)) & 0xFFu;
                float4 b0 = ((const float4*)w2p)[c8 * 2];
                float4 b1 = ((const float4*)w2p)[c8 * 2 + 1];
                float wv[8] = {b0.x, b0.y, b0.z, b0.w, b1.x, b1.y, b1.z, b1.w};
                float pv[8];
                #pragma unroll
                for (int q = 0; q < 8; q++) {
                    float p = 0.f;
                    if ((m8 >> q) & 1u) {
                        float e = w1r * wv[q];
                        e = e > 0.f ? e : 0.2f * e;
                        p = fexp(e - mr);
                    }
                    pv[q] = p;
                }
                uint32_t pk[4];
                #pragma unroll
                for (int qq = 0; qq < 4; qq++) {
                    __half2 hh = __floats2half2_rn(pv[2 * qq], pv[2 * qq + 1]);
                    pk[qq] = *reinterpret_cast<uint32_t*>(&hh);
                    float2 f2 = __half22float2(hh);
                    zp += f2.x + f2.y;
                }
                sts128(dst + c8 * 16, pk[0], pk[1], pk[2], pk[3]);
            }
        }
        __syncthreads();
        // ---- MMA: 2 k-steps of 16 ----
        #pragma unroll
        for (int ks = 0; ks < 2; ks++) {
            uint32_t afr[4][4];
            #pragma unroll
            for (int mi = 0; mi < 4; mi++)
                ldmA(afr[mi], aBase + (uint32_t)(mi * 16) * (SAP * 2) + (uint32_t)ks * 32);
            uint32_t bfr[4][2];
            #pragma unroll
            for (int ni = 0; ni < 4; ni++)
                ldmB(bfr[ni], bBase + (uint32_t)(ks * 16) * (SBP * 2) + (uint32_t)ni * 16);
            #pragma unroll
            for (int mi = 0; mi < 4; mi++)
                #pragma unroll
                for (int ni = 0; ni < 4; ni++)
                    mma16816(acc[mi][ni], afr[mi], bfr[ni]);
        }
    }

    // ---- epilogue: deterministic partials ----
    #pragma unroll
    for (int mi = 0; mi < 4; mi++) {
        int row0 = i0 + wm * 64 + mi * 16 + (lane >> 2);
        #pragma unroll
        for (int ni = 0; ni < 4; ni++) {
            int col = wn * 32 + ni * 8 + (lane & 3) * 2;
            *(float2*)&g_part[js][(size_t)row0 * G_ + col] =
                make_float2(acc[mi][ni][0], acc[mi][ni][1]);
            *(float2*)&g_part[js][(size_t)(row0 + 8) * G_ + col] =
                make_float2(acc[mi][ni][2], acc[mi][ni][3]);
        }
    }
    zp += __shfl_xor_sync(0xFFFFFFFFu, zp, 1);
    if (h == 0) g_Zpart[js][i0 + r] = zp;
}

// H = relu(sum partials / sum Z)
__global__ __launch_bounds__(256) void k_epi(float* __restrict__ dst, int toGlobal) {
    int idx = blockIdx.x * 256 + threadIdx.x;
    int i = idx >> 7;
    float s = 0.f, z = 0.f;
    #pragma unroll
    for (int t = 0; t < JSPLIT; t++) { s += g_part[t][idx]; z += g_Zpart[t][i]; }
    float h = s * frcp(z);
    h = h > 0.f ? h : 0.f;
    if (toGlobal) g_H[idx] = h; else dst[idx] = h;
}

// ---------------- launcher ----------------
extern "C" void kernel_launch(void* const* d_in, const int* in_sizes, int n_in,
                              void* d_out, int out_size) {
    const float* X    = (const float*)d_in[0];
    const float* gum  = (const float*)d_in[1];
    const float* alnk = (const float*)d_in[2];
    const float* Ws[2] = { (const float*)d_in[3], (const float*)d_in[4] };
    const float* Wq[2] = { (const float*)d_in[5], (const float*)d_in[6] };
    const float* Wv[2] = { (const float*)d_in[7], (const float*)d_in[8] };
    const float* aa[2] = { (const float*)d_in[9], (const float*)d_in[10] };
    float* out = (float*)d_out;

    float* Ap;
    if (out_size >= NG + NSQ) Ap = out + NG;
    else cudaGetSymbolAddress((void**)&Ap, g_Afb);

    k_A<<<NN_ / TIA, 256>>>(X, gum, alnk, Ap);

    for (int k = 0; k < 2; k++) {
        int F = (k == 0) ? FIN : G_;
        k_cvec<<<1, 128>>>(Wq[k], Wv[k], aa[k], F);
        k_wvec<<<NN_ / 8, 256>>>(X, k, F);
        k_mm<<<NN_ / 8, 256>>>();
        k_wh<<<NN_ / MT, 256>>>(X, Ws[k], k, F);
        dim3 ag(NN_ / MT, JSPLIT);
        k_attn_mma<<<ag, 256>>>();
        k_epi<<<NG / 256, 256>>>(out, k == 0 ? 1 : 0);
    }

    if (out_size >= NG + NSQ + NN_ * FIN)
        cudaMemcpyAsync(out + NG + NSQ, X, (size_t)NN_ * FIN * sizeof(float),
                        cudaMemcpyDeviceToDevice, 0);
}

// round 10
// speedup vs baseline: 1.6319x; 1.0145x over previous
#include <cuda_runtime.h>
#include <cuda_fp16.h>
#include <cstdint>

#define NN_ 2048
#define FIN 64
#define G_ 128
#define FOBS 32
#define NG (NN_*G_)
#define NSQ (NN_*NN_)
#define EPSF 1e-10f
#define TIA 8

#define MT 128
#define JSPLIT 8
#define KSPAN (NN_/JSPLIT)   // 256 j per block
#define KC 32                // j chunk
#define NCH (KSPAN/KC)       // 8

// SMEM padded strides (fp16 elems). Row strides are 16B multiples:
// SAP=40 -> 80B (conflict-free ldmatrix), SBP=136 -> 272B
#define SAP 40
#define SBP 136
#define ABYTES (MT*SAP*2)
#define BBYTES (KC*SBP*2)

// ---------------- scratch (static device, no allocs) ----------------
__device__ float g_Afb[NSQ];
__device__ float g_H[NG];
__device__ __half g_Whb[NG];                  // Wh fp16, [j][g] row-major
__device__ uint32_t g_mask[NN_][64];          // A>0.01 bitmask
__device__ float g_w1[NN_], g_w2[NN_], g_m[NN_];
__device__ float g_part[JSPLIT][NG];
__device__ float g_Zpart[JSPLIT][NN_];

// ---------------- FMA-pipe math (no MUFU) ----------------
__device__ __forceinline__ float fexp(float x) {
    float x2 = x * 1.4426950408889634f;
    x2 = fminf(fmaxf(x2, -126.0f), 126.0f);
    float r = x2 + 12582912.0f;
    int   n = __float_as_int(r) - 0x4B400000;
    float f = x2 - (r - 12582912.0f);
    float p = 1.5403512e-4f;
    p = fmaf(p, f, 1.33335574e-3f);
    p = fmaf(p, f, 9.61812911e-3f);
    p = fmaf(p, f, 5.55041087e-2f);
    p = fmaf(p, f, 2.40226507e-1f);
    p = fmaf(p, f, 6.93147181e-1f);
    p = fmaf(p, f, 1.0f);
    return p * __int_as_float((n + 127) << 23);
}

__device__ __forceinline__ float flog(float x) {
    int ix = __float_as_int(x);
    int e  = (ix >> 23) - 127;
    float m = __int_as_float((ix & 0x007FFFFF) | 0x3F800000);
    if (m > 1.41421356f) { m *= 0.5f; e += 1; }
    float f = m - 1.0f;
    float p = -0.1f;
    p = fmaf(p, f,  0.111111111f);
    p = fmaf(p, f, -0.125f);
    p = fmaf(p, f,  0.142857143f);
    p = fmaf(p, f, -0.166666667f);
    p = fmaf(p, f,  0.2f);
    p = fmaf(p, f, -0.25f);
    p = fmaf(p, f,  0.333333333f);
    p = fmaf(p, f, -0.5f);
    p = fmaf(p, f,  1.0f);
    p = p * f;
    return fmaf((float)e, 0.69314718056f, p);
}

__device__ __forceinline__ float frcp(float d) {
    float y = __int_as_float(0x7EF311C3 - __float_as_int(d));
    y = y * (2.0f - d * y);
    y = y * (2.0f - d * y);
    y = y * (2.0f - d * y);
    return y;
}

// ---------------- base-ISA tensor-core helpers ----------------
__device__ __forceinline__ uint32_t smem_u32(const void* p) {
    uint32_t a;
    asm("{ .reg .u64 t; cvta.to.shared.u64 t, %1; cvt.u32.u64 %0, t; }" : "=r"(a) : "l"(p));
    return a;
}
__device__ __forceinline__ void ldmA(uint32_t* a, uint32_t addr) {
    asm volatile("ldmatrix.sync.aligned.m8n8.x4.shared.b16 {%0,%1,%2,%3}, [%4];"
                 : "=r"(a[0]), "=r"(a[1]), "=r"(a[2]), "=r"(a[3]) : "r"(addr));
}
__device__ __forceinline__ void ldmB(uint32_t* b, uint32_t addr) {
    asm volatile("ldmatrix.sync.aligned.m8n8.x2.trans.shared.b16 {%0,%1}, [%2];"
                 : "=r"(b[0]), "=r"(b[1]) : "r"(addr));
}
__device__ __forceinline__ void mma16816(float* d, const uint32_t* a, const uint32_t* b) {
    asm volatile("mma.sync.aligned.m16n8k16.row.col.f32.f16.f16.f32 "
                 "{%0,%1,%2,%3}, {%4,%5,%6,%7}, {%8,%9}, {%0,%1,%2,%3};"
                 : "+f"(d[0]), "+f"(d[1]), "+f"(d[2]), "+f"(d[3])
                 : "r"(a[0]), "r"(a[1]), "r"(a[2]), "r"(a[3]), "r"(b[0]), "r"(b[1]));
}
__device__ __forceinline__ void sts128(uint32_t addr, uint32_t r0, uint32_t r1, uint32_t r2, uint32_t r3) {
    asm volatile("st.shared.v4.b32 [%0], {%1,%2,%3,%4};"
                 :: "r"(addr), "r"(r0), "r"(r1), "r"(r2), "r"(r3) : "memory");
}
__device__ __forceinline__ uint32_t h2u(float a, float b) {
    __half2 h = __floats2half2_rn(a, b);
    return *reinterpret_cast<uint32_t*>(&h);
}

// ---------------- Kernel 1: A matrix + mask ----------------
__global__ __launch_bounds__(256) void k_A(const float* __restrict__ X,
                                           const float* __restrict__ gum,
                                           const float* __restrict__ alink,
                                           float* __restrict__ Ap) {
    __shared__ float sh[TIA][FOBS];
    __shared__ float sa[FOBS];
    int tid = threadIdx.x;
    int i0  = blockIdx.x * TIA;
    if (tid < FOBS) sa[tid] = alink[tid];
    sh[tid >> 5][tid & 31] = X[(i0 + (tid >> 5)) * FIN + (tid & 31)];
    __syncthreads();

    for (int l = 0; l < NN_ / 256; l++) {
        int j = l * 256 + tid;
        float xj[FOBS];
        const float4* xp = (const float4*)(X + (size_t)j * FIN);
        #pragma unroll
        for (int q = 0; q < FOBS / 4; q++) ((float4*)xj)[q] = xp[q];

        #pragma unroll
        for (int ii = 0; ii < TIA; ii++) {
            float lgt = 0.f;
            #pragma unroll
            for (int k = 0; k < FOBS; k++)
                lgt = fmaf(fabsf(sh[ii][k] - xj[k]), sa[k], lgt);
            int i = i0 + ii;
            float u = gum[(size_t)i * NN_ + j];
            float t = EPSF - flog(u + EPSF);
            float t2 = t * t, t4 = t2 * t2, t8 = t4 * t4;
            float w = fexp(-10.f * lgt) * (t8 * t2);
            w = fminf(w, 1e30f);
            float A = frcp(1.0f + w);
            if (j == i) A = 1.0f;
            Ap[(size_t)i * NN_ + j] = A;
            uint32_t bal = __ballot_sync(0xFFFFFFFFu, A > 0.01f);
            if ((tid & 31) == 0) g_mask[i][(j >> 5)] = bal;
        }
    }
}

// ---------------- fused cvec + wvec: w1 = H@(Wq@a0), w2 = H@(Wv@a1) ----------------
// grid 64 blocks, 256 threads; each block recomputes cq/cv in smem, then 32 rows.
__global__ __launch_bounds__(256) void k_wvec(const float* __restrict__ Xp,
                                              const float* __restrict__ Wq,
                                              const float* __restrict__ Wv,
                                              const float* __restrict__ a,
                                              int hop, int F) {
    __shared__ float scq[G_], scv[G_];
    const float* H = hop ? g_H : Xp;
    int tid = threadIdx.x;
    if (tid < F) {
        float s = 0.f;
        const float* wr = Wq + (size_t)tid * G_;
        for (int g = 0; g < G_; g++) s = fmaf(wr[g], a[g], s);
        scq[tid] = s;
    } else if (tid >= 128 && tid < 128 + F) {
        int t = tid - 128;
        float s = 0.f;
        const float* wr = Wv + (size_t)t * G_;
        for (int g = 0; g < G_; g++) s = fmaf(wr[g], a[G_ + g], s);
        scv[t] = s;
    }
    __syncthreads();

    int wid = tid >> 5, lane = tid & 31;
    #pragma unroll
    for (int rr = 0; rr < 4; rr++) {
        int row = blockIdx.x * 32 + wid * 4 + rr;
        float s1 = 0.f, s2 = 0.f;
        for (int f = lane; f < F; f += 32) {
            float h = H[(size_t)row * F + f];
            s1 = fmaf(h, scq[f], s1);
            s2 = fmaf(h, scv[f], s2);
        }
        #pragma unroll
        for (int o = 16; o; o >>= 1) {
            s1 += __shfl_xor_sync(0xFFFFFFFFu, s1, o);
            s2 += __shfl_xor_sync(0xFFFFFFFFu, s2, o);
        }
        if (lane == 0) { g_w1[row] = s1; g_w2[row] = s2; }
    }
}

// row max of masked e: 4 warps per row (grid 1024, block = 2 rows x 4 warps).
// Warp q of a row covers w in [q*4, q*4+4); lane L owns j = w*128 + L*4 + qq.
__global__ __launch_bounds__(256) void k_mm() {
    __shared__ float smx[2][4], smn[2][4];
    int tid = threadIdx.x, wid = tid >> 5, lane = tid & 31;
    int rloc = wid >> 2;                 // 0/1
    int q    = wid & 3;                  // quarter of the j range
    int row  = blockIdx.x * 2 + rloc;
    uint32_t myw = g_mask[row][q * 16 + (lane & 15)];  // 16 words this warp needs
    int bsh = (lane & 7) * 4;
    float mx = -3.4e38f, mn = 3.4e38f;
    #pragma unroll
    for (int t = 0; t < 4; t++) {
        int w = q * 4 + t;
        uint32_t word = __shfl_sync(0xFFFFFFFFu, myw, t * 4 + (lane >> 3));
        float4 v = *(const float4*)&g_w2[w * 128 + lane * 4];
        float vv[4] = {v.x, v.y, v.z, v.w};
        #pragma unroll
        for (int qq = 0; qq < 4; qq++) {
            bool b = (word >> (bsh + qq)) & 1u;
            mx = fmaxf(mx, b ? vv[qq] : -3.4e38f);
            mn = fminf(mn, b ? vv[qq] :  3.4e38f);
        }
    }
    #pragma unroll
    for (int o = 16; o; o >>= 1) {
        mx = fmaxf(mx, __shfl_xor_sync(0xFFFFFFFFu, mx, o));
        mn = fminf(mn, __shfl_xor_sync(0xFFFFFFFFu, mn, o));
    }
    if (lane == 0) { smx[rloc][q] = mx; smn[rloc][q] = mn; }
    __syncthreads();
    if (tid < 2) {
        float fmx = fmaxf(fmaxf(smx[tid][0], smx[tid][1]), fmaxf(smx[tid][2], smx[tid][3]));
        float fmn = fminf(fminf(smn[tid][0], smn[tid][1]), fminf(smn[tid][2], smn[tid][3]));
        int r = blockIdx.x * 2 + tid;
        float w1 = g_w1[r];
        float e = w1 * (w1 >= 0.f ? fmx : fmn);
        e = e > 0.f ? e : 0.2f * e;
        g_m[r] = e;
    }
}

// ---------------- Wh = H @ Ws via fp16 mma, output fp16 [j][g] ----------------
__global__ __launch_bounds__(256) void k_wh(const float* __restrict__ Xp,
                                            const float* __restrict__ Ws,
                                            int hop, int F) {
    __shared__ __half sH[MT][SAP];
    __shared__ __half sW[16][SBP];
    const float* H = hop ? g_H : Xp;

    int tid = threadIdx.x, wid = tid >> 5, lane = tid & 31;
    int i0 = blockIdx.x * MT;
    int wm = wid >> 2, wn = wid & 3;

    uint32_t SHb = smem_u32(sH), SWb = smem_u32(sW);
    uint32_t aBase = SHb + (uint32_t)(wm * 64 + (lane & 15)) * (SAP * 2) + (uint32_t)((lane >> 4) * 16);
    uint32_t bBase = SWb + (uint32_t)(lane & 15) * (SBP * 2) + (uint32_t)(wn * 64);

    float acc[4][4][4];
    #pragma unroll
    for (int mi = 0; mi < 4; mi++)
        #pragma unroll
        for (int ni = 0; ni < 4; ni++)
            #pragma unroll
            for (int q = 0; q < 4; q++) acc[mi][ni][q] = 0.f;

    for (int f0 = 0; f0 < F; f0 += 16) {
        __syncthreads();
        {
            int row = tid >> 1, hh = tid & 1;
            const float* src = H + (size_t)(i0 + row) * F + f0 + hh * 8;
            float4 v0 = *(const float4*)src;
            float4 v1 = *(const float4*)(src + 4);
            sts128(SHb + (uint32_t)row * (SAP * 2) + (uint32_t)hh * 16,
                   h2u(v0.x, v0.y), h2u(v0.z, v0.w), h2u(v1.x, v1.y), h2u(v1.z, v1.w));
        }
        {
            int fr = tid >> 4, seg = tid & 15;
            const float* src = Ws + (size_t)(f0 + fr) * G_ + seg * 8;
            float4 v0 = *(const float4*)src;
            float4 v1 = *(const float4*)(src + 4);
            sts128(SWb + (uint32_t)fr * (SBP * 2) + (uint32_t)seg * 16,
                   h2u(v0.x, v0.y), h2u(v0.z, v0.w), h2u(v1.x, v1.y), h2u(v1.z, v1.w));
        }
        __syncthreads();
        uint32_t afr[4][4];
        #pragma unroll
        for (int mi = 0; mi < 4; mi++)
            ldmA(afr[mi], aBase + (uint32_t)(mi * 16) * (SAP * 2));
        uint32_t bfr[4][2];
        #pragma unroll
        for (int ni = 0; ni < 4; ni++)
            ldmB(bfr[ni], bBase + (uint32_t)ni * 16);
        #pragma unroll
        for (int mi = 0; mi < 4; mi++)
            #pragma unroll
            for (int ni = 0; ni < 4; ni++)
                mma16816(acc[mi][ni], afr[mi], bfr[ni]);
    }

    #pragma unroll
    for (int mi = 0; mi < 4; mi++) {
        int row0 = i0 + wm * 64 + mi * 16 + (lane >> 2);
        #pragma unroll
        for (int ni = 0; ni < 4; ni++) {
            int col = wn * 32 + ni * 8 + (lane & 3) * 2;
            __half2 h0 = __floats2half2_rn(acc[mi][ni][0], acc[mi][ni][1]);
            __half2 h1 = __floats2half2_rn(acc[mi][ni][2], acc[mi][ni][3]);
            *(__half2*)&g_Whb[(size_t)row0 * G_ + col] = h0;
            *(__half2*)&g_Whb[(size_t)(row0 + 8) * G_ + col] = h1;
        }
    }
}

// ---------------- fused P-generation + fp16 mma GEMM, double-buffered ----------------
// grid (16, JSPLIT), 256 threads (8 warps as 2m x 4n), out tile 128x128
__global__ __launch_bounds__(256) void k_attn_mma() {
    __shared__ __half sA[2][MT][SAP];    // P chunks, double buffered
    __shared__ __half sB[2][KC][SBP];    // Wh chunks

    int tid = threadIdx.x, wid = tid >> 5, lane = tid & 31;
    int i0 = blockIdx.x * MT;
    int js = blockIdx.y;
    int wm = wid >> 2, wn = wid & 3;

    uint32_t SAb = smem_u32(sA), SBb = smem_u32(sB);

    int r = tid >> 1, h = tid & 1;              // P-gen: row r, 16 cols at h*16
    float w1r = g_w1[i0 + r], mr = g_m[i0 + r];
    float zp = 0.f;

    float acc[4][4][4];
    #pragma unroll
    for (int mi = 0; mi < 4; mi++)
        #pragma unroll
        for (int ni = 0; ni < 4; ni++)
            #pragma unroll
            for (int q = 0; q < 4; q++) acc[mi][ni][q] = 0.f;

    uint32_t aBase = SAb + (uint32_t)(wm * 64 + (lane & 15)) * (SAP * 2) + (uint32_t)((lane >> 4) * 16);
    uint32_t bBase = SBb + (uint32_t)(lane & 15) * (SBP * 2) + (uint32_t)(wn * 64);

    // produce chunk cc into buffer p: B-tile load + P-gen
#define PRODUCE(cc, p) {                                                            \
        int j0 = js * KSPAN + (cc) * KC;                                            \
        uint32_t SBp = SBb + (uint32_t)(p) * BBYTES;                                \
        _Pragma("unroll")                                                           \
        for (int ps = 0; ps < 2; ps++) {                                            \
            int idx = ps * 256 + tid;                                               \
            int row = idx >> 4, c16 = idx & 15;                                     \
            uint4 v = *(const uint4*)&g_Whb[(size_t)(j0 + row) * G_ + c16 * 8];     \
            sts128(SBp + (uint32_t)row * (SBP * 2) + (uint32_t)c16 * 16,            \
                   v.x, v.y, v.z, v.w);                                             \
        }                                                                           \
        uint32_t mword = g_mask[i0 + r][js * 8 + (cc)];                             \
        uint32_t mh = (mword >> (h * 16)) & 0xFFFFu;                                \
        const float* w2p = g_w2 + j0 + h * 16;                                      \
        uint32_t dst = SAb + (uint32_t)(p) * ABYTES + (uint32_t)r * (SAP * 2)       \
                       + (uint32_t)h * 32;                                          \
        _Pragma("unroll")                                                           \
        for (int c8 = 0; c8 < 2; c8++) {                                            \
            uint32_t m8 = (mh >> (c8 * 8)) & 0xFFu;                                 \
            float4 b0 = ((const float4*)w2p)[c8 * 2];                               \
            float4 b1 = ((const float4*)w2p)[c8 * 2 + 1];                           \
            float wv[8] = {b0.x, b0.y, b0.z, b0.w, b1.x, b1.y, b1.z, b1.w};         \
            float pv[8];                                                            \
            _Pragma("unroll")                                                       \
            for (int q = 0; q < 8; q++) {                                           \
                float p_ = 0.f;                                                     \
                if ((m8 >> q) & 1u) {                                               \
                    float e = w1r * wv[q];                                          \
                    e = e > 0.f ? e : 0.2f * e;                                     \
                    p_ = fexp(e - mr);                                              \
                }                                                                   \
                pv[q] = p_;                                                         \
            }                                                                       \
            uint32_t pk[4];                                                         \
            _Pragma("unroll")                                                       \
            for (int qq = 0; qq < 4; qq++) {                                        \
                __half2 hh = __floats2half2_rn(pv[2 * qq], pv[2 * qq + 1]);         \
                pk[qq] = *reinterpret_cast<uint32_t*>(&hh);                         \
                float2 f2 = __half22float2(hh);                                     \
                zp += f2.x + f2.y;                                                  \
            }                                                                       \
            sts128(dst + c8 * 16, pk[0], pk[1], pk[2], pk[3]);                      \
        }                                                                           \
    }

    PRODUCE(0, 0);
    for (int cc = 0; cc < NCH; cc++) {
        int p = cc & 1;
        __syncthreads();                 // buffer p fully produced
        // ---- issue MMA on buffer p (tensor pipe drains during next produce) ----
        uint32_t aB = aBase + (uint32_t)p * ABYTES;
        uint32_t bB = bBase + (uint32_t)p * BBYTES;
        #pragma unroll
        for (int ks = 0; ks < 2; ks++) {
            uint32_t afr[4][4];
            #pragma unroll
            for (int mi = 0; mi < 4; mi++)
                ldmA(afr[mi], aB + (uint32_t)(mi * 16) * (SAP * 2) + (uint32_t)ks * 32);
            uint32_t bfr[4][2];
            #pragma unroll
            for (int ni = 0; ni < 4; ni++)
                ldmB(bfr[ni], bB + (uint32_t)(ks * 16) * (SBP * 2) + (uint32_t)ni * 16);
            #pragma unroll
            for (int mi = 0; mi < 4; mi++)
                #pragma unroll
                for (int ni = 0; ni < 4; ni++)
                    mma16816(acc[mi][ni], afr[mi], bfr[ni]);
        }
        if (cc + 1 < NCH) PRODUCE(cc + 1, p ^ 1);
    }
#undef PRODUCE

    // ---- epilogue: deterministic partials ----
    #pragma unroll
    for (int mi = 0; mi < 4; mi++) {
        int row0 = i0 + wm * 64 + mi * 16 + (lane >> 2);
        #pragma unroll
        for (int ni = 0; ni < 4; ni++) {
            int col = wn * 32 + ni * 8 + (lane & 3) * 2;
            *(float2*)&g_part[js][(size_t)row0 * G_ + col] =
                make_float2(acc[mi][ni][0], acc[mi][ni][1]);
            *(float2*)&g_part[js][(size_t)(row0 + 8) * G_ + col] =
                make_float2(acc[mi][ni][2], acc[mi][ni][3]);
        }
    }
    zp += __shfl_xor_sync(0xFFFFFFFFu, zp, 1);
    if (h == 0) g_Zpart[js][i0 + r] = zp;
}

// H = relu(sum partials / sum Z)
__global__ __launch_bounds__(256) void k_epi(float* __restrict__ dst, int toGlobal) {
    int idx = blockIdx.x * 256 + threadIdx.x;
    int i = idx >> 7;
    float s = 0.f, z = 0.f;
    #pragma unroll
    for (int t = 0; t < JSPLIT; t++) { s += g_part[t][idx]; z += g_Zpart[t][i]; }
    float h = s * frcp(z);
    h = h > 0.f ? h : 0.f;
    if (toGlobal) g_H[idx] = h; else dst[idx] = h;
}

// ---------------- launcher ----------------
extern "C" void kernel_launch(void* const* d_in, const int* in_sizes, int n_in,
                              void* d_out, int out_size) {
    const float* X    = (const float*)d_in[0];
    const float* gum  = (const float*)d_in[1];
    const float* alnk = (const float*)d_in[2];
    const float* Ws[2] = { (const float*)d_in[3], (const float*)d_in[4] };
    const float* Wq[2] = { (const float*)d_in[5], (const float*)d_in[6] };
    const float* Wv[2] = { (const float*)d_in[7], (const float*)d_in[8] };
    const float* aa[2] = { (const float*)d_in[9], (const float*)d_in[10] };
    float* out = (float*)d_out;

    float* Ap;
    if (out_size >= NG + NSQ) Ap = out + NG;
    else cudaGetSymbolAddress((void**)&Ap, g_Afb);

    k_A<<<NN_ / TIA, 256>>>(X, gum, alnk, Ap);

    for (int k = 0; k < 2; k++) {
        int F = (k == 0) ? FIN : G_;
        k_wvec<<<NN_ / 32, 256>>>(X, Wq[k], Wv[k], aa[k], k, F);
        k_mm<<<NN_ / 2, 256>>>();
        k_wh<<<NN_ / MT, 256>>>(X, Ws[k], k, F);
        dim3 ag(NN_ / MT, JSPLIT);
        k_attn_mma<<<ag, 256>>>();
        k_epi<<<NG / 256, 256>>>(out, k == 0 ? 1 : 0);
    }

    if (out_size >= NG + NSQ + NN_ * FIN)
        cudaMemcpyAsync(out + NG + NSQ, X, (size_t)NN_ * FIN * sizeof(float),
                        cudaMemcpyDeviceToDevice, 0);
}

// round 12
// speedup vs baseline: 1.8187x; 1.1145x over previous
#include <cuda_runtime.h>
#include <cuda_fp16.h>
#include <cstdint>

#define NN_ 2048
#define FIN 64
#define G_ 128
#define FOBS 32
#define NG (NN_*G_)
#define NSQ (NN_*NN_)
#define EPSF 1e-10f
#define TIA 8

#define MT 128
#define JSPLIT 8
#define KSPAN (NN_/JSPLIT)   // 256 j per block
#define KC 32                // j chunk
#define NCH (KSPAN/KC)       // 8

// SMEM padded strides (fp16 elems). Row strides are 16B multiples:
// SAP=40 -> 80B (conflict-free ldmatrix), SBP=136 -> 272B, SHP=136 (k_prep H tile)
#define SAP 40
#define SBP 136
#define SHP 136
#define ABYTES (MT*SAP*2)
#define BBYTES (KC*SBP*2)

// ---------------- scratch (static device, no allocs) ----------------
__device__ float g_Afb[NSQ];
__device__ float g_H[NG];
__device__ __half g_Whb[NG];                  // Wh fp16, [j][g] row-major
__device__ uint32_t g_mask[NN_][64];          // A>0.01 bitmask
__device__ float g_w1[NN_], g_w2[NN_], g_m[NN_];
__device__ float g_part[JSPLIT][NG];
__device__ float g_Zpart[JSPLIT][NN_];

// ---------------- FMA-pipe math (no MUFU) ----------------
__device__ __forceinline__ float fexp(float x) {
    float x2 = x * 1.4426950408889634f;
    x2 = fminf(fmaxf(x2, -126.0f), 126.0f);
    float r = x2 + 12582912.0f;
    int   n = __float_as_int(r) - 0x4B400000;
    float f = x2 - (r - 12582912.0f);
    float p = 1.5403512e-4f;
    p = fmaf(p, f, 1.33335574e-3f);
    p = fmaf(p, f, 9.61812911e-3f);
    p = fmaf(p, f, 5.55041087e-2f);
    p = fmaf(p, f, 2.40226507e-1f);
    p = fmaf(p, f, 6.93147181e-1f);
    p = fmaf(p, f, 1.0f);
    return p * __int_as_float((n + 127) << 23);
}

__device__ __forceinline__ float flog(float x) {
    int ix = __float_as_int(x);
    int e  = (ix >> 23) - 127;
    float m = __int_as_float((ix & 0x007FFFFF) | 0x3F800000);
    if (m > 1.41421356f) { m *= 0.5f; e += 1; }
    float f = m - 1.0f;
    float p = -0.1f;
    p = fmaf(p, f,  0.111111111f);
    p = fmaf(p, f, -0.125f);
    p = fmaf(p, f,  0.142857143f);
    p = fmaf(p, f, -0.166666667f);
    p = fmaf(p, f,  0.2f);
    p = fmaf(p, f, -0.25f);
    p = fmaf(p, f,  0.333333333f);
    p = fmaf(p, f, -0.5f);
    p = fmaf(p, f,  1.0f);
    p = p * f;
    return fmaf((float)e, 0.69314718056f, p);
}

__device__ __forceinline__ float frcp(float d) {
    float y = __int_as_float(0x7EF311C3 - __float_as_int(d));
    y = y * (2.0f - d * y);
    y = y * (2.0f - d * y);
    y = y * (2.0f - d * y);
    return y;
}

// ---------------- base-ISA tensor-core helpers ----------------
__device__ __forceinline__ uint32_t smem_u32(const void* p) {
    uint32_t a;
    asm("{ .reg .u64 t; cvta.to.shared.u64 t, %1; cvt.u32.u64 %0, t; }" : "=r"(a) : "l"(p));
    return a;
}
__device__ __forceinline__ void ldmA(uint32_t* a, uint32_t addr) {
    asm volatile("ldmatrix.sync.aligned.m8n8.x4.shared.b16 {%0,%1,%2,%3}, [%4];"
                 : "=r"(a[0]), "=r"(a[1]), "=r"(a[2]), "=r"(a[3]) : "r"(addr));
}
__device__ __forceinline__ void ldmB(uint32_t* b, uint32_t addr) {
    asm volatile("ldmatrix.sync.aligned.m8n8.x2.trans.shared.b16 {%0,%1}, [%2];"
                 : "=r"(b[0]), "=r"(b[1]) : "r"(addr));
}
__device__ __forceinline__ void mma16816(float* d, const uint32_t* a, const uint32_t* b) {
    asm volatile("mma.sync.aligned.m16n8k16.row.col.f32.f16.f16.f32 "
                 "{%0,%1,%2,%3}, {%4,%5,%6,%7}, {%8,%9}, {%0,%1,%2,%3};"
                 : "+f"(d[0]), "+f"(d[1]), "+f"(d[2]), "+f"(d[3])
                 : "r"(a[0]), "r"(a[1]), "r"(a[2]), "r"(a[3]), "r"(b[0]), "r"(b[1]));
}
__device__ __forceinline__ void sts128(uint32_t addr, uint32_t r0, uint32_t r1, uint32_t r2, uint32_t r3) {
    asm volatile("st.shared.v4.b32 [%0], {%1,%2,%3,%4};"
                 :: "r"(addr), "r"(r0), "r"(r1), "r"(r2), "r"(r3) : "memory");
}
__device__ __forceinline__ uint32_t h2u(float a, float b) {
    __half2 h = __floats2half2_rn(a, b);
    return *reinterpret_cast<uint32_t*>(&h);
}

// ---------------- Kernel 1: A matrix + mask ----------------
__global__ __launch_bounds__(256) void k_A(const float* __restrict__ X,
                                           const float* __restrict__ gum,
                                           const float* __restrict__ alink,
                                           float* __restrict__ Ap) {
    __shared__ float sh[TIA][FOBS];
    __shared__ float sa[FOBS];
    int tid = threadIdx.x;
    int i0  = blockIdx.x * TIA;
    if (tid < FOBS) sa[tid] = alink[tid];
    sh[tid >> 5][tid & 31] = X[(i0 + (tid >> 5)) * FIN + (tid & 31)];
    __syncthreads();

    for (int l = 0; l < NN_ / 256; l++) {
        int j = l * 256 + tid;
        float xj[FOBS];
        const float4* xp = (const float4*)(X + (size_t)j * FIN);
        #pragma unroll
        for (int q = 0; q < FOBS / 4; q++) ((float4*)xj)[q] = xp[q];

        #pragma unroll
        for (int ii = 0; ii < TIA; ii++) {
            float lgt = 0.f;
            #pragma unroll
            for (int k = 0; k < FOBS; k++)
                lgt = fmaf(fabsf(sh[ii][k] - xj[k]), sa[k], lgt);
            int i = i0 + ii;
            float u = gum[(size_t)i * NN_ + j];
            float t = EPSF - flog(u + EPSF);
            float t2 = t * t, t4 = t2 * t2, t8 = t4 * t4;
            float w = fexp(-10.f * lgt) * (t8 * t2);
            w = fminf(w, 1e30f);
            float A = frcp(1.0f + w);
            if (j == i) A = 1.0f;
            Ap[(size_t)i * NN_ + j] = A;
            uint32_t bal = __ballot_sync(0xFFFFFFFFu, A > 0.01f);
            if ((tid & 31) == 0) g_mask[i][(j >> 5)] = bal;
        }
    }
}

// ---------------- fused prep: wvec (blocks 0-63) + Wh mma GEMM (blocks 64-127) ----------------
__global__ __launch_bounds__(256) void k_prep(const float* __restrict__ Xp,
                                              const float* __restrict__ Wq,
                                              const float* __restrict__ Wv,
                                              const float* __restrict__ a,
                                              const float* __restrict__ Ws,
                                              int hop, int F) {
    __shared__ float scq[G_], scv[G_];
    __shared__ __half sH[32][SHP];        // 32 rows x up to 128 halves (272B stride)
    __shared__ __half sW[G_][SBP];
    const float* H = hop ? g_H : Xp;
    int tid = threadIdx.x, wid = tid >> 5, lane = tid & 31;

    if (blockIdx.x < 64) {
        // ---- wvec: w1 = H@(Wq@a0), w2 = H@(Wv@a1), 32 rows per block ----
        if (tid < F) {
            float s = 0.f;
            const float* wr = Wq + (size_t)tid * G_;
            for (int g = 0; g < G_; g++) s = fmaf(wr[g], a[g], s);
            scq[tid] = s;
        } else if (tid >= 128 && tid < 128 + F) {
            int t = tid - 128;
            float s = 0.f;
            const float* wr = Wv + (size_t)t * G_;
            for (int g = 0; g < G_; g++) s = fmaf(wr[g], a[G_ + g], s);
            scv[t] = s;
        }
        __syncthreads();
        #pragma unroll
        for (int rr = 0; rr < 4; rr++) {
            int row = blockIdx.x * 32 + wid * 4 + rr;
            float s1 = 0.f, s2 = 0.f;
            for (int f = lane; f < F; f += 32) {
                float h = H[(size_t)row * F + f];
                s1 = fmaf(h, scq[f], s1);
                s2 = fmaf(h, scv[f], s2);
            }
            #pragma unroll
            for (int o = 16; o; o >>= 1) {
                s1 += __shfl_xor_sync(0xFFFFFFFFu, s1, o);
                s2 += __shfl_xor_sync(0xFFFFFFFFu, s2, o);
            }
            if (lane == 0) { g_w1[row] = s1; g_w2[row] = s2; }
        }
    } else {
        // ---- Wh GEMM: 32 output rows per block, whole K in smem, one barrier ----
        int i0 = (blockIdx.x - 64) * 32;
        uint32_t SHb = smem_u32(sH), SWb = smem_u32(sW);
        // load H tile 32 x F (fp32 -> fp16), row stride SHP
        int segsH = 32 * (F / 8);
        for (int s = tid; s < segsH; s += 256) {
            int row = s / (F / 8), seg = s % (F / 8);
            const float* src = H + (size_t)(i0 + row) * F + seg * 8;
            float4 v0 = *(const float4*)src;
            float4 v1 = *(const float4*)(src + 4);
            sts128(SHb + (uint32_t)row * (SHP * 2) + (uint32_t)seg * 16,
                   h2u(v0.x, v0.y), h2u(v0.z, v0.w), h2u(v1.x, v1.y), h2u(v1.z, v1.w));
        }
        // load Ws F x 128 (fp32 -> fp16)
        for (int s = tid; s < F * 16; s += 256) {
            int row = s >> 4, seg = s & 15;
            const float* src = Ws + (size_t)row * G_ + seg * 8;
            float4 v0 = *(const float4*)src;
            float4 v1 = *(const float4*)(src + 4);
            sts128(SWb + (uint32_t)row * (SBP * 2) + (uint32_t)seg * 16,
                   h2u(v0.x, v0.y), h2u(v0.z, v0.w), h2u(v1.x, v1.y), h2u(v1.z, v1.w));
        }
        __syncthreads();

        int wm = wid >> 2, wn = wid & 3;          // warp tile: rows wm*16, cols wn*32
        uint32_t aBase = SHb + (uint32_t)(wm * 16 + (lane & 15)) * (SHP * 2) + (uint32_t)((lane >> 4) * 16);
        uint32_t bBase = SWb + (uint32_t)(lane & 15) * (SBP * 2) + (uint32_t)(wn * 64);

        float acc[4][4];
        #pragma unroll
        for (int ni = 0; ni < 4; ni++)
            #pragma unroll
            for (int q = 0; q < 4; q++) acc[ni][q] = 0.f;

        for (int ks = 0; ks < F / 16; ks++) {
            uint32_t afr[4];
            ldmA(afr, aBase + (uint32_t)ks * 32);
            uint32_t bfr[4][2];
            #pragma unroll
            for (int ni = 0; ni < 4; ni++)
                ldmB(bfr[ni], bBase + (uint32_t)(ks * 16) * (SBP * 2) + (uint32_t)ni * 16);
            #pragma unroll
            for (int ni = 0; ni < 4; ni++)
                mma16816(acc[ni], afr, bfr[ni]);
        }

        int row0 = i0 + wm * 16 + (lane >> 2);
        #pragma unroll
        for (int ni = 0; ni < 4; ni++) {
            int col = wn * 32 + ni * 8 + (lane & 3) * 2;
            __half2 h0 = __floats2half2_rn(acc[ni][0], acc[ni][1]);
            __half2 h1 = __floats2half2_rn(acc[ni][2], acc[ni][3]);
            *(__half2*)&g_Whb[(size_t)row0 * G_ + col] = h0;
            *(__half2*)&g_Whb[(size_t)(row0 + 8) * G_ + col] = h1;
        }
    }
}

// row max of masked e: 4 warps per row (grid 1024, block = 2 rows x 4 warps).
__global__ __launch_bounds__(256) void k_mm() {
    __shared__ float smx[2][4], smn[2][4];
    int tid = threadIdx.x, wid = tid >> 5, lane = tid & 31;
    int rloc = wid >> 2;                 // 0/1
    int q    = wid & 3;                  // quarter of the j range
    int row  = blockIdx.x * 2 + rloc;
    uint32_t myw = g_mask[row][q * 16 + (lane & 15)];  // 16 words this warp needs
    int bsh = (lane & 7) * 4;
    float mx = -3.4e38f, mn = 3.4e38f;
    #pragma unroll
    for (int t = 0; t < 4; t++) {
        int w = q * 4 + t;
        uint32_t word = __shfl_sync(0xFFFFFFFFu, myw, t * 4 + (lane >> 3));
        float4 v = *(const float4*)&g_w2[w * 128 + lane * 4];
        float vv[4] = {v.x, v.y, v.z, v.w};
        #pragma unroll
        for (int qq = 0; qq < 4; qq++) {
            bool b = (word >> (bsh + qq)) & 1u;
            mx = fmaxf(mx, b ? vv[qq] : -3.4e38f);
            mn = fminf(mn, b ? vv[qq] :  3.4e38f);
        }
    }
    #pragma unroll
    for (int o = 16; o; o >>= 1) {
        mx = fmaxf(mx, __shfl_xor_sync(0xFFFFFFFFu, mx, o));
        mn = fminf(mn, __shfl_xor_sync(0xFFFFFFFFu, mn, o));
    }
    if (lane == 0) { smx[rloc][q] = mx; smn[rloc][q] = mn; }
    __syncthreads();
    if (tid < 2) {
        float fmx = fmaxf(fmaxf(smx[tid][0], smx[tid][1]), fmaxf(smx[tid][2], smx[tid][3]));
        float fmn = fminf(fminf(smn[tid][0], smn[tid][1]), fminf(smn[tid][2], smn[tid][3]));
        int r = blockIdx.x * 2 + tid;
        float w1 = g_w1[r];
        float e = w1 * (w1 >= 0.f ? fmx : fmn);
        e = e > 0.f ? e : 0.2f * e;
        g_m[r] = e;
    }
}

// ---------------- fused P-generation + fp16 mma GEMM, double-buffered ----------------
// grid (16, JSPLIT), 256 threads (8 warps as 2m x 4n), out tile 128x128
__global__ __launch_bounds__(256) void k_attn_mma() {
    __shared__ __half sA[2][MT][SAP];    // P chunks, double buffered
    __shared__ __half sB[2][KC][SBP];    // Wh chunks

    int tid = threadIdx.x, wid = tid >> 5, lane = tid & 31;
    int i0 = blockIdx.x * MT;
    int js = blockIdx.y;
    int wm = wid >> 2, wn = wid & 3;

    uint32_t SAb = smem_u32(sA), SBb = smem_u32(sB);

    int r = tid >> 1, h = tid & 1;              // P-gen: row r, 16 cols at h*16
    float w1r = g_w1[i0 + r], mr = g_m[i0 + r];
    float zp = 0.f;

    float acc[4][4][4];
    #pragma unroll
    for (int mi = 0; mi < 4; mi++)
        #pragma unroll
        for (int ni = 0; ni < 4; ni++)
            #pragma unroll
            for (int q = 0; q < 4; q++) acc[mi][ni][q] = 0.f;

    uint32_t aBase = SAb + (uint32_t)(wm * 64 + (lane & 15)) * (SAP * 2) + (uint32_t)((lane >> 4) * 16);
    uint32_t bBase = SBb + (uint32_t)(lane & 15) * (SBP * 2) + (uint32_t)(wn * 64);

    // produce chunk cc into buffer p: B-tile load + P-gen
#define PRODUCE(cc, p) {                                                            \
        int j0 = js * KSPAN + (cc) * KC;                                            \
        uint32_t SBp = SBb + (uint32_t)(p) * BBYTES;                                \
        _Pragma("unroll")                                                           \
        for (int ps = 0; ps < 2; ps++) {                                            \
            int idx = ps * 256 + tid;                                               \
            int row = idx >> 4, c16 = idx & 15;                                     \
            uint4 v = *(const uint4*)&g_Whb[(size_t)(j0 + row) * G_ + c16 * 8];     \
            sts128(SBp + (uint32_t)row * (SBP * 2) + (uint32_t)c16 * 16,            \
                   v.x, v.y, v.z, v.w);                                             \
        }                                                                           \
        uint32_t mword = g_mask[i0 + r][js * 8 + (cc)];                             \
        uint32_t mh = (mword >> (h * 16)) & 0xFFFFu;                                \
        const float* w2p = g_w2 + j0 + h * 16;                                      \
        uint32_t dst = SAb + (uint32_t)(p) * ABYTES + (uint32_t)r * (SAP * 2)       \
                       + (uint32_t)h * 32;                                          \
        _Pragma("unroll")                                                           \
        for (int c8 = 0; c8 < 2; c8++) {                                            \
            uint32_t m8 = (mh >> (c8 * 8)) & 0xFFu;                                 \
            float4 b0 = ((const float4*)w2p)[c8 * 2];                               \
            float4 b1 = ((const float4*)w2p)[c8 * 2 + 1];                           \
            float wv[8] = {b0.x, b0.y, b0.z, b0.w, b1.x, b1.y, b1.z, b1.w};         \
            float pv[8];                                                            \
            _Pragma("unroll")                                                       \
            for (int q = 0; q < 8; q++) {                                           \
                float p_ = 0.f;                                                     \
                if ((m8 >> q) & 1u) {                                               \
                    float e = w1r * wv[q];                                          \
                    e = e > 0.f ? e : 0.2f * e;                                     \
                    p_ = fexp(e - mr);                                              \
                }                                                                   \
                pv[q] = p_;                                                         \
            }                                                                       \
            uint32_t pk[4];                                                         \
            _Pragma("unroll")                                                       \
            for (int qq = 0; qq < 4; qq++) {                                        \
                __half2 hh = __floats2half2_rn(pv[2 * qq], pv[2 * qq + 1]);         \
                pk[qq] = *reinterpret_cast<uint32_t*>(&hh);                         \
                float2 f2 = __half22float2(hh);                                     \
                zp += f2.x + f2.y;                                                  \
            }                                                                       \
            sts128(dst + c8 * 16, pk[0], pk[1], pk[2], pk[3]);                      \
        }                                                                           \
    }

    PRODUCE(0, 0);
    for (int cc = 0; cc < NCH; cc++) {
        int p = cc & 1;
        __syncthreads();                 // buffer p fully produced
        uint32_t aB = aBase + (uint32_t)p * ABYTES;
        uint32_t bB = bBase + (uint32_t)p * BBYTES;
        #pragma unroll
        for (int ks = 0; ks < 2; ks++) {
            uint32_t afr[4][4];
            #pragma unroll
            for (int mi = 0; mi < 4; mi++)
                ldmA(afr[mi], aB + (uint32_t)(mi * 16) * (SAP * 2) + (uint32_t)ks * 32);
            uint32_t bfr[4][2];
            #pragma unroll
            for (int ni = 0; ni < 4; ni++)
                ldmB(bfr[ni], bB + (uint32_t)(ks * 16) * (SBP * 2) + (uint32_t)ni * 16);
            #pragma unroll
            for (int mi = 0; mi < 4; mi++)
                #pragma unroll
                for (int ni = 0; ni < 4; ni++)
                    mma16816(acc[mi][ni], afr[mi], bfr[ni]);
        }
        if (cc + 1 < NCH) PRODUCE(cc + 1, p ^ 1);
    }
#undef PRODUCE

    // ---- epilogue: deterministic partials ----
    #pragma unroll
    for (int mi = 0; mi < 4; mi++) {
        int row0 = i0 + wm * 64 + mi * 16 + (lane >> 2);
        #pragma unroll
        for (int ni = 0; ni < 4; ni++) {
            int col = wn * 32 + ni * 8 + (lane & 3) * 2;
            *(float2*)&g_part[js][(size_t)row0 * G_ + col] =
                make_float2(acc[mi][ni][0], acc[mi][ni][1]);
            *(float2*)&g_part[js][(size_t)(row0 + 8) * G_ + col] =
                make_float2(acc[mi][ni][2], acc[mi][ni][3]);
        }
    }
    zp += __shfl_xor_sync(0xFFFFFFFFu, zp, 1);
    if (h == 0) g_Zpart[js][i0 + r] = zp;
}

// H = relu(sum partials / sum Z)
__global__ __launch_bounds__(256) void k_epi(float* __restrict__ dst, int toGlobal) {
    int idx = blockIdx.x * 256 + threadIdx.x;
    int i = idx >> 7;
    float s = 0.f, z = 0.f;
    #pragma unroll
    for (int t = 0; t < JSPLIT; t++) { s += g_part[t][idx]; z += g_Zpart[t][i]; }
    float h = s * frcp(z);
    h = h > 0.f ? h : 0.f;
    if (toGlobal) g_H[idx] = h; else dst[idx] = h;
}

// ---------------- launcher ----------------
extern "C" void kernel_launch(void* const* d_in, const int* in_sizes, int n_in,
                              void* d_out, int out_size) {
    const float* X    = (const float*)d_in[0];
    const float* gum  = (const float*)d_in[1];
    const float* alnk = (const float*)d_in[2];
    const float* Ws[2] = { (const float*)d_in[3], (const float*)d_in[4] };
    const float* Wq[2] = { (const float*)d_in[5], (const float*)d_in[6] };
    const float* Wv[2] = { (const float*)d_in[7], (const float*)d_in[8] };
    const float* aa[2] = { (const float*)d_in[9], (const float*)d_in[10] };
    float* out = (float*)d_out;

    float* Ap;
    if (out_size >= NG + NSQ) Ap = out + NG;
    else cudaGetSymbolAddress((void**)&Ap, g_Afb);

    k_A<<<NN_ / TIA, 256>>>(X, gum, alnk, Ap);

    for (int k = 0; k < 2; k++) {
        int F = (k == 0) ? FIN : G_;
        k_prep<<<128, 256>>>(X, Wq[k], Wv[k], aa[k], Ws[k], k, F);
        k_mm<<<NN_ / 2, 256>>>();
        dim3 ag(NN_ / MT, JSPLIT);
        k_attn_mma<<<ag, 256>>>();
        k_epi<<<NG / 256, 256>>>(out, k == 0 ? 1 : 0);
    }

    if (out_size >= NG + NSQ + NN_ * FIN)
        cudaMemcpyAsync(out + NG + NSQ, X, (size_t)NN_ * FIN * sizeof(float),
                        cudaMemcpyDeviceToDevice, 0);
}

// round 13
// speedup vs baseline: 2.0125x; 1.1065x over previous
#include <cuda_runtime.h>
#include <cuda_fp16.h>
#include <cstdint>

#define NN_ 2048
#define FIN 64
#define G_ 128
#define FOBS 32
#define NG (NN_*G_)
#define NSQ (NN_*NN_)
#define EPSF 1e-10f
#define TIA 8

#define MT 128
#define JSPLIT 16
#define KSPAN (NN_/JSPLIT)   // 128 j per block
#define KC 32                // j chunk
#define NCH (KSPAN/KC)       // 4
#define WPS (KSPAN/32)       // mask words per j-span = 4

// SMEM padded strides (fp16 elems). Row strides are 16B multiples:
// SAP=40 -> 80B (conflict-free ldmatrix), SBP=136 -> 272B, SHP=136 (k_prep H tile)
#define SAP 40
#define SBP 136
#define SHP 136
#define ABYTES (MT*SAP*2)
#define BBYTES (KC*SBP*2)

// ---------------- scratch (static device, no allocs) ----------------
__device__ float g_Afb[NSQ];
__device__ float g_H[NG];
__device__ __half g_Whb[NG];                  // Wh fp16, [j][g] row-major
__device__ uint32_t g_mask[NN_][64];          // A>0.01 bitmask
__device__ float g_w1[NN_], g_w2[NN_], g_m[NN_];
__device__ float g_part[JSPLIT][NG];
__device__ float g_Zpart[JSPLIT][NN_];

// ---------------- FMA-pipe math (no MUFU) ----------------
__device__ __forceinline__ float fexp(float x) {
    float x2 = x * 1.4426950408889634f;
    x2 = fminf(fmaxf(x2, -126.0f), 126.0f);
    float r = x2 + 12582912.0f;
    int   n = __float_as_int(r) - 0x4B400000;
    float f = x2 - (r - 12582912.0f);
    float p = 1.5403512e-4f;
    p = fmaf(p, f, 1.33335574e-3f);
    p = fmaf(p, f, 9.61812911e-3f);
    p = fmaf(p, f, 5.55041087e-2f);
    p = fmaf(p, f, 2.40226507e-1f);
    p = fmaf(p, f, 6.93147181e-1f);
    p = fmaf(p, f, 1.0f);
    return p * __int_as_float((n + 127) << 23);
}

__device__ __forceinline__ float flog(float x) {
    int ix = __float_as_int(x);
    int e  = (ix >> 23) - 127;
    float m = __int_as_float((ix & 0x007FFFFF) | 0x3F800000);
    if (m > 1.41421356f) { m *= 0.5f; e += 1; }
    float f = m - 1.0f;
    float p = -0.1f;
    p = fmaf(p, f,  0.111111111f);
    p = fmaf(p, f, -0.125f);
    p = fmaf(p, f,  0.142857143f);
    p = fmaf(p, f, -0.166666667f);
    p = fmaf(p, f,  0.2f);
    p = fmaf(p, f, -0.25f);
    p = fmaf(p, f,  0.333333333f);
    p = fmaf(p, f, -0.5f);
    p = fmaf(p, f,  1.0f);
    p = p * f;
    return fmaf((float)e, 0.69314718056f, p);
}

__device__ __forceinline__ float frcp(float d) {
    float y = __int_as_float(0x7EF311C3 - __float_as_int(d));
    y = y * (2.0f - d * y);
    y = y * (2.0f - d * y);
    y = y * (2.0f - d * y);
    return y;
}

// ---------------- base-ISA tensor-core helpers ----------------
__device__ __forceinline__ uint32_t smem_u32(const void* p) {
    uint32_t a;
    asm("{ .reg .u64 t; cvta.to.shared.u64 t, %1; cvt.u32.u64 %0, t; }" : "=r"(a) : "l"(p));
    return a;
}
__device__ __forceinline__ void ldmA(uint32_t* a, uint32_t addr) {
    asm volatile("ldmatrix.sync.aligned.m8n8.x4.shared.b16 {%0,%1,%2,%3}, [%4];"
                 : "=r"(a[0]), "=r"(a[1]), "=r"(a[2]), "=r"(a[3]) : "r"(addr));
}
__device__ __forceinline__ void ldmB(uint32_t* b, uint32_t addr) {
    asm volatile("ldmatrix.sync.aligned.m8n8.x2.trans.shared.b16 {%0,%1}, [%2];"
                 : "=r"(b[0]), "=r"(b[1]) : "r"(addr));
}
__device__ __forceinline__ void mma16816(float* d, const uint32_t* a, const uint32_t* b) {
    asm volatile("mma.sync.aligned.m16n8k16.row.col.f32.f16.f16.f32 "
                 "{%0,%1,%2,%3}, {%4,%5,%6,%7}, {%8,%9}, {%0,%1,%2,%3};"
                 : "+f"(d[0]), "+f"(d[1]), "+f"(d[2]), "+f"(d[3])
                 : "r"(a[0]), "r"(a[1]), "r"(a[2]), "r"(a[3]), "r"(b[0]), "r"(b[1]));
}
__device__ __forceinline__ void sts128(uint32_t addr, uint32_t r0, uint32_t r1, uint32_t r2, uint32_t r3) {
    asm volatile("st.shared.v4.b32 [%0], {%1,%2,%3,%4};"
                 :: "r"(addr), "r"(r0), "r"(r1), "r"(r2), "r"(r3) : "memory");
}
__device__ __forceinline__ uint32_t h2u(float a, float b) {
    __half2 h = __floats2half2_rn(a, b);
    return *reinterpret_cast<uint32_t*>(&h);
}

// ---------------- Kernel 1: A matrix + mask ----------------
__global__ __launch_bounds__(256) void k_A(const float* __restrict__ X,
                                           const float* __restrict__ gum,
                                           const float* __restrict__ alink,
                                           float* __restrict__ Ap) {
    __shared__ float sh[TIA][FOBS];
    __shared__ float sa[FOBS];
    int tid = threadIdx.x;
    int i0  = blockIdx.x * TIA;
    if (tid < FOBS) sa[tid] = alink[tid];
    sh[tid >> 5][tid & 31] = X[(i0 + (tid >> 5)) * FIN + (tid & 31)];
    __syncthreads();

    for (int l = 0; l < NN_ / 256; l++) {
        int j = l * 256 + tid;
        float xj[FOBS];
        const float4* xp = (const float4*)(X + (size_t)j * FIN);
        #pragma unroll
        for (int q = 0; q < FOBS / 4; q++) ((float4*)xj)[q] = xp[q];

        #pragma unroll
        for (int ii = 0; ii < TIA; ii++) {
            float lgt = 0.f;
            #pragma unroll
            for (int k = 0; k < FOBS; k++)
                lgt = fmaf(fabsf(sh[ii][k] - xj[k]), sa[k], lgt);
            int i = i0 + ii;
            float u = gum[(size_t)i * NN_ + j];
            float t = EPSF - flog(u + EPSF);
            float t2 = t * t, t4 = t2 * t2, t8 = t4 * t4;
            float w = fexp(-10.f * lgt) * (t8 * t2);
            w = fminf(w, 1e30f);
            float A = frcp(1.0f + w);
            if (j == i) A = 1.0f;
            Ap[(size_t)i * NN_ + j] = A;
            uint32_t bal = __ballot_sync(0xFFFFFFFFu, A > 0.01f);
            if ((tid & 31) == 0) g_mask[i][(j >> 5)] = bal;
        }
    }
}

// ---------------- fused prep: wvec (blocks 0-63) + Wh mma GEMM (blocks 64-127) ----------------
__global__ __launch_bounds__(256) void k_prep(const float* __restrict__ Xp,
                                              const float* __restrict__ Wq,
                                              const float* __restrict__ Wv,
                                              const float* __restrict__ a,
                                              const float* __restrict__ Ws,
                                              int hop, int F) {
    __shared__ float scq[G_], scv[G_];
    __shared__ __half sH[32][SHP];        // 32 rows x up to 128 halves (272B stride)
    __shared__ __half sW[G_][SBP];
    const float* H = hop ? g_H : Xp;
    int tid = threadIdx.x, wid = tid >> 5, lane = tid & 31;

    if (blockIdx.x < 64) {
        // ---- wvec: w1 = H@(Wq@a0), w2 = H@(Wv@a1), 32 rows per block ----
        if (tid < F) {
            float s = 0.f;
            const float* wr = Wq + (size_t)tid * G_;
            for (int g = 0; g < G_; g++) s = fmaf(wr[g], a[g], s);
            scq[tid] = s;
        } else if (tid >= 128 && tid < 128 + F) {
            int t = tid - 128;
            float s = 0.f;
            const float* wr = Wv + (size_t)t * G_;
            for (int g = 0; g < G_; g++) s = fmaf(wr[g], a[G_ + g], s);
            scv[t] = s;
        }
        __syncthreads();
        #pragma unroll
        for (int rr = 0; rr < 4; rr++) {
            int row = blockIdx.x * 32 + wid * 4 + rr;
            float s1 = 0.f, s2 = 0.f;
            for (int f = lane; f < F; f += 32) {
                float h = H[(size_t)row * F + f];
                s1 = fmaf(h, scq[f], s1);
                s2 = fmaf(h, scv[f], s2);
            }
            #pragma unroll
            for (int o = 16; o; o >>= 1) {
                s1 += __shfl_xor_sync(0xFFFFFFFFu, s1, o);
                s2 += __shfl_xor_sync(0xFFFFFFFFu, s2, o);
            }
            if (lane == 0) { g_w1[row] = s1; g_w2[row] = s2; }
        }
    } else {
        // ---- Wh GEMM: 32 output rows per block, whole K in smem, one barrier ----
        int i0 = (blockIdx.x - 64) * 32;
        uint32_t SHb = smem_u32(sH), SWb = smem_u32(sW);
        int segsH = 32 * (F / 8);
        for (int s = tid; s < segsH; s += 256) {
            int row = s / (F / 8), seg = s % (F / 8);
            const float* src = H + (size_t)(i0 + row) * F + seg * 8;
            float4 v0 = *(const float4*)src;
            float4 v1 = *(const float4*)(src + 4);
            sts128(SHb + (uint32_t)row * (SHP * 2) + (uint32_t)seg * 16,
                   h2u(v0.x, v0.y), h2u(v0.z, v0.w), h2u(v1.x, v1.y), h2u(v1.z, v1.w));
        }
        for (int s = tid; s < F * 16; s += 256) {
            int row = s >> 4, seg = s & 15;
            const float* src = Ws + (size_t)row * G_ + seg * 8;
            float4 v0 = *(const float4*)src;
            float4 v1 = *(const float4*)(src + 4);
            sts128(SWb + (uint32_t)row * (SBP * 2) + (uint32_t)seg * 16,
                   h2u(v0.x, v0.y), h2u(v0.z, v0.w), h2u(v1.x, v1.y), h2u(v1.z, v1.w));
        }
        __syncthreads();

        int wm = wid >> 2, wn = wid & 3;
        uint32_t aBase = SHb + (uint32_t)(wm * 16 + (lane & 15)) * (SHP * 2) + (uint32_t)((lane >> 4) * 16);
        uint32_t bBase = SWb + (uint32_t)(lane & 15) * (SBP * 2) + (uint32_t)(wn * 64);

        float acc[4][4];
        #pragma unroll
        for (int ni = 0; ni < 4; ni++)
            #pragma unroll
            for (int q = 0; q < 4; q++) acc[ni][q] = 0.f;

        for (int ks = 0; ks < F / 16; ks++) {
            uint32_t afr[4];
            ldmA(afr, aBase + (uint32_t)ks * 32);
            uint32_t bfr[4][2];
            #pragma unroll
            for (int ni = 0; ni < 4; ni++)
                ldmB(bfr[ni], bBase + (uint32_t)(ks * 16) * (SBP * 2) + (uint32_t)ni * 16);
            #pragma unroll
            for (int ni = 0; ni < 4; ni++)
                mma16816(acc[ni], afr, bfr[ni]);
        }

        int row0 = i0 + wm * 16 + (lane >> 2);
        #pragma unroll
        for (int ni = 0; ni < 4; ni++) {
            int col = wn * 32 + ni * 8 + (lane & 3) * 2;
            __half2 h0 = __floats2half2_rn(acc[ni][0], acc[ni][1]);
            __half2 h1 = __floats2half2_rn(acc[ni][2], acc[ni][3]);
            *(__half2*)&g_Whb[(size_t)row0 * G_ + col] = h0;
            *(__half2*)&g_Whb[(size_t)(row0 + 8) * G_ + col] = h1;
        }
    }
}

// row max of masked e: 4 warps per row (grid 1024, block = 2 rows x 4 warps).
__global__ __launch_bounds__(256) void k_mm() {
    __shared__ float smx[2][4], smn[2][4];
    int tid = threadIdx.x, wid = tid >> 5, lane = tid & 31;
    int rloc = wid >> 2;
    int q    = wid & 3;
    int row  = blockIdx.x * 2 + rloc;
    uint32_t myw = g_mask[row][q * 16 + (lane & 15)];
    int bsh = (lane & 7) * 4;
    float mx = -3.4e38f, mn = 3.4e38f;
    #pragma unroll
    for (int t = 0; t < 4; t++) {
        int w = q * 4 + t;
        uint32_t word = __shfl_sync(0xFFFFFFFFu, myw, t * 4 + (lane >> 3));
        float4 v = *(const float4*)&g_w2[w * 128 + lane * 4];
        float vv[4] = {v.x, v.y, v.z, v.w};
        #pragma unroll
        for (int qq = 0; qq < 4; qq++) {
            bool b = (word >> (bsh + qq)) & 1u;
            mx = fmaxf(mx, b ? vv[qq] : -3.4e38f);
            mn = fminf(mn, b ? vv[qq] :  3.4e38f);
        }
    }
    #pragma unroll
    for (int o = 16; o; o >>= 1) {
        mx = fmaxf(mx, __shfl_xor_sync(0xFFFFFFFFu, mx, o));
        mn = fminf(mn, __shfl_xor_sync(0xFFFFFFFFu, mn, o));
    }
    if (lane == 0) { smx[rloc][q] = mx; smn[rloc][q] = mn; }
    __syncthreads();
    if (tid < 2) {
        float fmx = fmaxf(fmaxf(smx[tid][0], smx[tid][1]), fmaxf(smx[tid][2], smx[tid][3]));
        float fmn = fminf(fminf(smn[tid][0], smn[tid][1]), fminf(smn[tid][2], smn[tid][3]));
        int r = blockIdx.x * 2 + tid;
        float w1 = g_w1[r];
        float e = w1 * (w1 >= 0.f ? fmx : fmn);
        e = e > 0.f ? e : 0.2f * e;
        g_m[r] = e;
    }
}

// ---------------- fused P-generation + fp16 mma GEMM, reg-prefetch pipeline ----------------
// grid (16, JSPLIT=16), 256 threads (8 warps as 2m x 4n), out tile 128x128
__global__ __launch_bounds__(256, 2) void k_attn_mma() {
    __shared__ __half sA[2][MT][SAP];    // P chunks, double buffered
    __shared__ __half sB[2][KC][SBP];    // Wh chunks

    int tid = threadIdx.x, wid = tid >> 5, lane = tid & 31;
    int i0 = blockIdx.x * MT;
    int js = blockIdx.y;
    int wm = wid >> 2, wn = wid & 3;

    uint32_t SAb = smem_u32(sA), SBb = smem_u32(sB);

    int r = tid >> 1, h = tid & 1;              // P-gen: row r, 16 cols at h*16
    int brow = tid >> 4, bc16 = tid & 15;       // B-tile load mapping
    float w1r = g_w1[i0 + r], mr = g_m[i0 + r];
    float zp = 0.f;

    float acc[4][4][4];
    #pragma unroll
    for (int mi = 0; mi < 4; mi++)
        #pragma unroll
        for (int ni = 0; ni < 4; ni++)
            #pragma unroll
            for (int q = 0; q < 4; q++) acc[mi][ni][q] = 0.f;

    uint32_t aBase = SAb + (uint32_t)(wm * 64 + (lane & 15)) * (SAP * 2) + (uint32_t)((lane >> 4) * 16);
    uint32_t bBase = SBb + (uint32_t)(lane & 15) * (SBP * 2) + (uint32_t)(wn * 64);

    // prefetch registers
    uint4 pb0, pb1;
    uint32_t pmw;
    float4 pw[4];

#define LOADCH(cc) {                                                                \
        int j0 = js * KSPAN + (cc) * KC;                                            \
        pb0 = *(const uint4*)&g_Whb[(size_t)(j0 + brow) * G_ + bc16 * 8];           \
        pb1 = *(const uint4*)&g_Whb[(size_t)(j0 + 16 + brow) * G_ + bc16 * 8];      \
        pmw = g_mask[i0 + r][js * WPS + (cc)];                                      \
        const float4* w2p = (const float4*)(g_w2 + j0 + h * 16);                    \
        pw[0] = w2p[0]; pw[1] = w2p[1]; pw[2] = w2p[2]; pw[3] = w2p[3];             \
    }

#define STORECH(p) {                                                                \
        uint32_t SBp = SBb + (uint32_t)(p) * BBYTES;                                \
        sts128(SBp + (uint32_t)brow * (SBP * 2) + (uint32_t)bc16 * 16,              \
               pb0.x, pb0.y, pb0.z, pb0.w);                                         \
        sts128(SBp + (uint32_t)(brow + 16) * (SBP * 2) + (uint32_t)bc16 * 16,       \
               pb1.x, pb1.y, pb1.z, pb1.w);                                         \
        uint32_t mh = (pmw >> (h * 16)) & 0xFFFFu;                                  \
        uint32_t dst = SAb + (uint32_t)(p) * ABYTES + (uint32_t)r * (SAP * 2)       \
                       + (uint32_t)h * 32;                                          \
        _Pragma("unroll")                                                           \
        for (int c8 = 0; c8 < 2; c8++) {                                            \
            uint32_t m8 = (mh >> (c8 * 8)) & 0xFFu;                                 \
            float4 b0 = pw[c8 * 2];                                                 \
            float4 b1 = pw[c8 * 2 + 1];                                             \
            float wv[8] = {b0.x, b0.y, b0.z, b0.w, b1.x, b1.y, b1.z, b1.w};         \
            float pv[8];                                                            \
            _Pragma("unroll")                                                       \
            for (int q = 0; q < 8; q++) {                                           \
                float p_ = 0.f;                                                     \
                if ((m8 >> q) & 1u) {                                               \
                    float e = w1r * wv[q];                                          \
                    e = e > 0.f ? e : 0.2f * e;                                     \
                    p_ = fexp(e - mr);                                              \
                }                                                                   \
                pv[q] = p_;                                                         \
            }                                                                       \
            uint32_t pk[4];                                                         \
            _Pragma("unroll")                                                       \
            for (int qq = 0; qq < 4; qq++) {                                        \
                __half2 hh = __floats2half2_rn(pv[2 * qq], pv[2 * qq + 1]);         \
                pk[qq] = *reinterpret_cast<uint32_t*>(&hh);                         \
                float2 f2 = __half22float2(hh);                                     \
                zp += f2.x + f2.y;                                                  \
            }                                                                       \
            sts128(dst + c8 * 16, pk[0], pk[1], pk[2], pk[3]);                      \
        }                                                                           \
    }

    LOADCH(0);
    #pragma unroll
    for (int cc = 0; cc < NCH; cc++) {
        int p = cc & 1;
        STORECH(p);                      // regs -> smem buffer p
        __syncthreads();                 // buffer p ready (and prior MMA on p done)
        if (cc + 1 < NCH) LOADCH(cc + 1);   // LDGs overlap with MMA below
        uint32_t aB = aBase + (uint32_t)p * ABYTES;
        uint32_t bB = bBase + (uint32_t)p * BBYTES;
        #pragma unroll
        for (int ks = 0; ks < 2; ks++) {
            uint32_t afr[4][4];
            #pragma unroll
            for (int mi = 0; mi < 4; mi++)
                ldmA(afr[mi], aB + (uint32_t)(mi * 16) * (SAP * 2) + (uint32_t)ks * 32);
            uint32_t bfr[4][2];
            #pragma unroll
            for (int ni = 0; ni < 4; ni++)
                ldmB(bfr[ni], bB + (uint32_t)(ks * 16) * (SBP * 2) + (uint32_t)ni * 16);
            #pragma unroll
            for (int mi = 0; mi < 4; mi++)
                #pragma unroll
                for (int ni = 0; ni < 4; ni++)
                    mma16816(acc[mi][ni], afr[mi], bfr[ni]);
        }
    }
#undef LOADCH
#undef STORECH

    // ---- epilogue: deterministic partials ----
    #pragma unroll
    for (int mi = 0; mi < 4; mi++) {
        int row0 = i0 + wm * 64 + mi * 16 + (lane >> 2);
        #pragma unroll
        for (int ni = 0; ni < 4; ni++) {
            int col = wn * 32 + ni * 8 + (lane & 3) * 2;
            *(float2*)&g_part[js][(size_t)row0 * G_ + col] =
                make_float2(acc[mi][ni][0], acc[mi][ni][1]);
            *(float2*)&g_part[js][(size_t)(row0 + 8) * G_ + col] =
                make_float2(acc[mi][ni][2], acc[mi][ni][3]);
        }
    }
    zp += __shfl_xor_sync(0xFFFFFFFFu, zp, 1);
    if (h == 0) g_Zpart[js][i0 + r] = zp;
}

// H = relu(sum partials / sum Z)
__global__ __launch_bounds__(256) void k_epi(float* __restrict__ dst, int toGlobal) {
    int idx = blockIdx.x * 256 + threadIdx.x;
    int i = idx >> 7;
    float s = 0.f, z = 0.f;
    #pragma unroll
    for (int t = 0; t < JSPLIT; t++) { s += g_part[t][idx]; z += g_Zpart[t][i]; }
    float h = s * frcp(z);
    h = h > 0.f ? h : 0.f;
    if (toGlobal) g_H[idx] = h; else dst[idx] = h;
}

// ---------------- launcher ----------------
extern "C" void kernel_launch(void* const* d_in, const int* in_sizes, int n_in,
                              void* d_out, int out_size) {
    const float* X    = (const float*)d_in[0];
    const float* gum  = (const float*)d_in[1];
    const float* alnk = (const float*)d_in[2];
    const float* Ws[2] = { (const float*)d_in[3], (const float*)d_in[4] };
    const float* Wq[2] = { (const float*)d_in[5], (const float*)d_in[6] };
    const float* Wv[2] = { (const float*)d_in[7], (const float*)d_in[8] };
    const float* aa[2] = { (const float*)d_in[9], (const float*)d_in[10] };
    float* out = (float*)d_out;

    float* Ap;
    if (out_size >= NG + NSQ) Ap = out + NG;
    else cudaGetSymbolAddress((void**)&Ap, g_Afb);

    k_A<<<NN_ / TIA, 256>>>(X, gum, alnk, Ap);

    for (int k = 0; k < 2; k++) {
        int F = (k == 0) ? FIN : G_;
        k_prep<<<128, 256>>>(X, Wq[k], Wv[k], aa[k], Ws[k], k, F);
        k_mm<<<NN_ / 2, 256>>>();
        dim3 ag(NN_ / MT, JSPLIT);
        k_attn_mma<<<ag, 256>>>();
        k_epi<<<NG / 256, 256>>>(out, k == 0 ? 1 : 0);
    }

    if (out_size >= NG + NSQ + NN_ * FIN)
        cudaMemcpyAsync(out + NG + NSQ, X, (size_t)NN_ * FIN * sizeof(float),
                        cudaMemcpyDeviceToDevice, 0);
}